// round 5
// baseline (speedup 1.0000x reference)
#include <cuda_runtime.h>
#include <cstdint>

#define NB 64
#define DIN 64
#define DH 128
#define TM 128

// float offsets in dynamic smem
#define SMF_W1  0            // 9*32*36 = 10368 floats
#define SMF_W2  10368        // 16*32*36 = 18432
#define SMF_BUF 28800        // A(10368) then H(18432) share: 18432
#define SMF_B2  47232        // 128
#define SMF_SB  47360        // 2*128 ints
#define SMF_TOT 47616
#define SMEM_BYTES (SMF_TOT*4)

__device__ float g_psum[NB*4];
__device__ unsigned long long g_amin[NB];
__device__ __align__(16) float g_cg[NB*DH];
__device__ __align__(16) float g_W1f[9*32*36];
__device__ __align__(16) float g_W2f[16*32*36];

__device__ __forceinline__ unsigned f2tf(float x){
    unsigned u; asm("cvt.rna.tf32.f32 %0, %1;" : "=r"(u) : "f"(x)); return u;
}
__device__ __forceinline__ void atomicMaxF(float* a, float v){
    if (v >= 0.f) atomicMax((int*)a, __float_as_int(v));
    else          atomicMin((unsigned int*)a, __float_as_uint(v));
}
__device__ __forceinline__ void mma8(float (&c)[4], const unsigned (&a)[4], unsigned b0, unsigned b1){
    asm volatile("mma.sync.aligned.m16n8k8.row.col.f32.tf32.tf32.f32 "
        "{%0,%1,%2,%3}, {%4,%5,%6,%7}, {%8,%9}, {%0,%1,%2,%3};\n"
        : "+f"(c[0]), "+f"(c[1]), "+f"(c[2]), "+f"(c[3])
        : "r"(a[0]), "r"(a[1]), "r"(a[2]), "r"(a[3]), "r"(b0), "r"(b1));
}

// ---------------------------------------------------------------------------
__global__ void k_init(float* out, int out_size){
    int i = blockIdx.x*blockDim.x + threadIdx.x;
    if (i < NB*4) g_psum[i] = 0.f;
    if (i < NB)   g_amin[i] = 0xFFFFFFFFFFFFFFFFULL;
    if (i < NB*DH && i < out_size) out[i] = __int_as_float(0xff800000);
}

__global__ void k_com(const float* __restrict__ pos, const int* __restrict__ batch, int n){
    int i = blockIdx.x*blockDim.x + threadIdx.x;
    int b = -1; float px=0.f, py=0.f, pz=0.f, pc=0.f;
    if (i < n){ b = batch[i]; px = pos[3*i]; py = pos[3*i+1]; pz = pos[3*i+2]; pc = 1.f; }
    int b0 = __shfl_sync(0xffffffffu, b, 0);
    bool uni = __all_sync(0xffffffffu, b == b0);
    if (uni){
        #pragma unroll
        for (int o = 16; o; o >>= 1){
            px += __shfl_down_sync(0xffffffffu, px, o);
            py += __shfl_down_sync(0xffffffffu, py, o);
            pz += __shfl_down_sync(0xffffffffu, pz, o);
            pc += __shfl_down_sync(0xffffffffu, pc, o);
        }
        if ((threadIdx.x & 31) == 0 && b0 >= 0){
            atomicAdd(&g_psum[b0*4+0], px); atomicAdd(&g_psum[b0*4+1], py);
            atomicAdd(&g_psum[b0*4+2], pz); atomicAdd(&g_psum[b0*4+3], pc);
        }
    } else if (b >= 0){
        atomicAdd(&g_psum[b*4+0], px); atomicAdd(&g_psum[b*4+1], py);
        atomicAdd(&g_psum[b*4+2], pz); atomicAdd(&g_psum[b*4+3], pc);
    }
}

__global__ void k_amin(const float* __restrict__ pos, const int* __restrict__ batch, int n){
    int i = blockIdx.x*blockDim.x + threadIdx.x;
    int b = -1; unsigned long long key = 0xFFFFFFFFFFFFFFFFULL;
    if (i < n){
        b = batch[i];
        float cnt = fmaxf(g_psum[b*4+3], 1.f);
        float inv = 1.f / cnt;
        float dx = pos[3*i]   - g_psum[b*4+0]*inv;
        float dy = pos[3*i+1] - g_psum[b*4+1]*inv;
        float dz = pos[3*i+2] - g_psum[b*4+2]*inv;
        float d2 = dx*dx + dy*dy + dz*dz;
        key = ((unsigned long long)__float_as_uint(d2) << 32) | (unsigned)i;
    }
    int b0 = __shfl_sync(0xffffffffu, b, 0);
    bool uni = __all_sync(0xffffffffu, b == b0);
    if (uni){
        #pragma unroll
        for (int o = 16; o; o >>= 1){
            unsigned long long k2 = __shfl_down_sync(0xffffffffu, key, o);
            if (k2 < key) key = k2;
        }
        if ((threadIdx.x & 31) == 0 && b0 >= 0) atomicMin(&g_amin[b0], key);
    } else if (b >= 0){
        atomicMin(&g_amin[b], key);
    }
}

// fragment-ordered, tf32-rounded weights
__global__ void k_wprep(const float* __restrict__ W1, const float* __restrict__ W2){
    int idx = blockIdx.x*blockDim.x + threadIdx.x;
    if (idx < 72*128){
        int k = idx >> 7, c = idx & 127;
        float v = 0.f;
        if (k < 64)      v = W1[(64+k)*DH + c];
        else if (k < 67) v = W1[(128 + (k-64))*DH + c];
        int ks = k>>3, tig = k&3, b = (k>>2)&1;
        int wn = c>>6, nt = (c>>3)&7, gid = c&7;
        int lane = gid*4 + tig, jp = nt>>1;
        int gsw = (wn*4 + jp) ^ (gid & 3);
        g_W1f[(ks*32 + lane)*36 + gsw*4 + (nt&1)*2 + b] = __uint_as_float(f2tf(v));
    } else if (idx < 72*128 + 128*128){
        int j = idx - 72*128;
        int k = j >> 7, c = j & 127;
        float v = W2[k*DH + c];
        int ks = k>>3, tig = k&3, b = (k>>2)&1;
        int wn = c>>6, nt = (c>>3)&7, gid = c&7;
        int lane = gid*4 + tig, jp = nt>>1;
        int gsw = (wn*4 + jp) ^ (gid & 3);
        g_W2f[(ks*32 + lane)*36 + gsw*4 + (nt&1)*2 + b] = __uint_as_float(f2tf(v));
    }
}

// per-graph bias cg + aux outputs
__global__ void k_prep(const float* __restrict__ x, const float* __restrict__ pos,
                       const int* __restrict__ batch, const float* __restrict__ lf,
                       const float* __restrict__ W1, const float* __restrict__ b1,
                       float* out, int out_size, int n){
    int g = blockIdx.x, c = threadIdx.x;
    __shared__ float sxd[DIN];
    __shared__ float sp3[3];
    __shared__ int sidx;
    if (c == 0){
        int id = (int)(unsigned)(g_amin[g] & 0xFFFFFFFFULL);
        if (id > n-1) id = n-1;
        sidx = id;
    }
    __syncthreads();
    int idx = sidx;
    if (c < DIN) sxd[c] = x[(size_t)idx*DIN + c];
    if (c < 3)   sp3[c] = pos[idx*3 + c];
    __syncthreads();
    float acc = b1[c];
    #pragma unroll 8
    for (int k = 0; k < DIN; k++)
        acc += sxd[k] * (W1[k*DH + c] - W1[(DIN+k)*DH + c]);
    #pragma unroll
    for (int j = 0; j < 3; j++)
        acc -= sp3[j] * W1[(2*DIN+j)*DH + c];
    g_cg[g*DH + c] = acc;

    if (out_size >= NB*DH + NB*3 + NB + NB*9){
        if (c < 3)  out[NB*DH + g*3 + c] = pos[idx*3 + c];
        if (c == 3) out[NB*DH + NB*3 + g] = (float)batch[idx];
        if (c < 9)  out[NB*DH + NB*3 + NB + g*9 + c] = lf[(size_t)idx*9 + c];
    }
}

// ---------------------------------------------------------------------------
struct APre {
    float4 v[8];
    float px, py, pz;
    int g;
};

__device__ __forceinline__ void ldA(APre& a, const float* __restrict__ x,
                                    const float* __restrict__ pos,
                                    const int* __restrict__ batch,
                                    int n, int row, int lkb, int lhalf){
    if (row < n){
        const float4* xr = (const float4*)(x + (size_t)row*DIN + lkb);
        #pragma unroll
        for (int i = 0; i < 8; i++) a.v[i] = xr[i];
        if (lhalf == 0){
            a.px = pos[row*3]; a.py = pos[row*3+1]; a.pz = pos[row*3+2];
            a.g = batch[row];
        }
    } else {
        #pragma unroll
        for (int i = 0; i < 8; i++) a.v[i] = make_float4(0.f,0.f,0.f,0.f);
        a.px = a.py = a.pz = 0.f;
        a.g = -1;
    }
}

__device__ __forceinline__ void stA(const APre& a, float* __restrict__ sBuf,
                                    int* __restrict__ sSB, int slot,
                                    int TB, int lkb, int lhalf, int lr){
    const float* vv = (const float*)a.v;
    int kbase = (lkb >> 3) * 1152;      // ks offset of first chunk
    #pragma unroll
    for (int j = 0; j < 32; j++){
        int Cj = kbase + (j>>3)*1152 + (j&3)*36 + ((j>>2)&1)*1;
        sBuf[TB + Cj] = vv[j];
    }
    if (lhalf == 0){
        // pos k-step (ks=8): k=64..66 pos, 67..71 zeros
        #pragma unroll
        for (int j = 0; j < 8; j++){
            float v = (j==0) ? a.px : (j==1) ? a.py : (j==2) ? a.pz : 0.f;
            sBuf[TB + 8*1152 + (j&3)*36 + ((j>>2)&1)] = v;
        }
        sSB[slot*128 + lr] = a.g;
    }
}

__global__ __launch_bounds__(256, 1)
void k_main(const float* __restrict__ x, const float* __restrict__ pos,
            const int* __restrict__ batch, const float* __restrict__ b2,
            float* __restrict__ out, int n)
{
    extern __shared__ float sm[];
    float* sW1 = sm + SMF_W1;
    float* sW2 = sm + SMF_W2;
    float* sBuf = sm + SMF_BUF;
    float* sB2 = sm + SMF_B2;
    int*   sSB = (int*)(sm + SMF_SB);

    const int tid = threadIdx.x, warp = tid >> 5, lane = tid & 31;
    const int gid = lane >> 2, tig = lane & 3;
    const int wm = warp >> 1, wn = warp & 1;
    const int swz = gid & 3;
    const int numTiles = (n + TM - 1) / TM;

    // weights + b2 to smem
    {
        const float4* s1 = (const float4*)g_W1f; float4* d1 = (float4*)sW1;
        for (int i = tid; i < 9*32*36/4; i += 256) d1[i] = s1[i];
        const float4* s2 = (const float4*)g_W2f; float4* d2 = (float4*)sW2;
        for (int i = tid; i < 16*32*36/4; i += 256) d2[i] = s2[i];
        if (tid < DH) sB2[tid] = b2[tid];
    }

    // loader thread params
    const int lr = tid >> 1, lhalf = tid & 1, lkb = lhalf*32;
    const int gidL = lr & 7, rhiL = (lr>>3)&1, GL = (lr>>4)&7;
    const int TB = gidL*144 + ((GL ^ (gidL & 3)) << 2) + rhiL*2;

    APre pre;
    const int t0 = blockIdx.x;
    if (t0 < numTiles){
        ldA(pre, x, pos, batch, n, t0*TM + lr, lkb, lhalf);
        stA(pre, sBuf, sSB, 0, TB, lkb, lhalf, lr);
    }
    __syncthreads();

    int it = 0;
    for (int t = t0; t < numTiles; t += 148, it++){
        const int par = it & 1;
        const int tn = t + 148;
        const bool hasNext = tn < numTiles;
        if (hasNext) ldA(pre, x, pos, batch, n, tn*TM + lr, lkb, lhalf);

        // ===== layer 1: acc1 = A @ W1 =====
        float acc1[2][8][4];
        #pragma unroll
        for (int mt = 0; mt < 2; mt++)
            #pragma unroll
            for (int nt = 0; nt < 8; nt++)
                #pragma unroll
                for (int q = 0; q < 4; q++) acc1[mt][nt][q] = 0.f;

        #pragma unroll
        for (int ks = 0; ks < 9; ks++){
            const float* cell = sBuf + ks*1152 + lane*36;
            float4 A0 = *(const float4*)(cell + (((wm*2+0) ^ swz) << 2));
            float4 A1 = *(const float4*)(cell + (((wm*2+1) ^ swz) << 2));
            unsigned a0[4] = {__float_as_uint(A0.x), __float_as_uint(A0.z),
                              __float_as_uint(A0.y), __float_as_uint(A0.w)};
            unsigned a1[4] = {__float_as_uint(A1.x), __float_as_uint(A1.z),
                              __float_as_uint(A1.y), __float_as_uint(A1.w)};
            const float* wcell = sW1 + ks*1152 + lane*36;
            #pragma unroll
            for (int jp = 0; jp < 4; jp++){
                float4 w = *(const float4*)(wcell + (((wn*4+jp) ^ swz) << 2));
                mma8(acc1[0][jp*2],   a0, __float_as_uint(w.x), __float_as_uint(w.y));
                mma8(acc1[1][jp*2],   a1, __float_as_uint(w.x), __float_as_uint(w.y));
                mma8(acc1[0][jp*2+1], a0, __float_as_uint(w.z), __float_as_uint(w.w));
                mma8(acc1[1][jp*2+1], a1, __float_as_uint(w.z), __float_as_uint(w.w));
            }
        }
        __syncthreads();   // (1) all A reads done

        // ===== epilogue 1: h = relu(acc1 + cg[g]) -> H frags in sBuf =====
        {
            const int r0 = wm*32 + gid;
            const int gg[2][2] = {{sSB[par*128 + r0],      sSB[par*128 + r0 + 8]},
                                  {sSB[par*128 + r0 + 16], sSB[par*128 + r0 + 24]}};
            const bool sameg = (gg[0][0]==gg[0][1]) & (gg[0][1]==gg[1][0]) & (gg[1][0]==gg[1][1]);
            const int khiT = tig >> 1;
            const int lane2b = gid*4 + (tig & 1)*2;

            if (sameg){
                const float* cgp = g_cg + (size_t)(gg[0][0] < 0 ? 0 : gg[0][0])*DH;
                float cgv[8][2];
                #pragma unroll
                for (int nt = 0; nt < 8; nt++)
                    #pragma unroll
                    for (int qc = 0; qc < 2; qc++)
                        cgv[nt][qc] = __ldg(cgp + wn*64 + nt*8 + tig*2 + qc);
                #pragma unroll
                for (int mt = 0; mt < 2; mt++){
                    const int gbase = (((wm*2+mt) ^ swz) << 2);
                    #pragma unroll
                    for (int nt = 0; nt < 8; nt++){
                        float* hc = sBuf + (wn*8+nt)*1152 + gbase + khiT;
                        #pragma unroll
                        for (int q = 0; q < 4; q++){
                            float h = fmaxf(acc1[mt][nt][q] + cgv[nt][q&1], 0.f);
                            hc[(lane2b + (q&1))*36 + (q>>1)*2] = h;
                        }
                    }
                }
            } else {
                const float* cgp[2][2];
                #pragma unroll
                for (int mt = 0; mt < 2; mt++)
                    #pragma unroll
                    for (int qr = 0; qr < 2; qr++)
                        cgp[mt][qr] = g_cg + (size_t)(gg[mt][qr] < 0 ? 0 : gg[mt][qr])*DH;
                #pragma unroll
                for (int mt = 0; mt < 2; mt++){
                    const int gbase = (((wm*2+mt) ^ swz) << 2);
                    #pragma unroll
                    for (int nt = 0; nt < 8; nt++){
                        float* hc = sBuf + (wn*8+nt)*1152 + gbase + khiT;
                        #pragma unroll
                        for (int q = 0; q < 4; q++){
                            int c = wn*64 + nt*8 + tig*2 + (q&1);
                            float h = fmaxf(acc1[mt][nt][q] + __ldg(cgp[mt][q>>1] + c), 0.f);
                            hc[(lane2b + (q&1))*36 + (q>>1)*2] = h;
                        }
                    }
                }
            }
        }
        __syncthreads();   // (2) H ready

        // ===== layer 2: acc2 = H @ W2 =====
        float acc2[2][8][4];
        #pragma unroll
        for (int mt = 0; mt < 2; mt++)
            #pragma unroll
            for (int nt = 0; nt < 8; nt++)
                #pragma unroll
                for (int q = 0; q < 4; q++) acc2[mt][nt][q] = 0.f;

        #pragma unroll
        for (int ks = 0; ks < 16; ks++){
            const float* cell = sBuf + ks*1152 + lane*36;
            float4 A0 = *(const float4*)(cell + (((wm*2+0) ^ swz) << 2));
            float4 A1 = *(const float4*)(cell + (((wm*2+1) ^ swz) << 2));
            unsigned a0[4] = {__float_as_uint(A0.x), __float_as_uint(A0.z),
                              __float_as_uint(A0.y), __float_as_uint(A0.w)};
            unsigned a1[4] = {__float_as_uint(A1.x), __float_as_uint(A1.z),
                              __float_as_uint(A1.y), __float_as_uint(A1.w)};
            const float* wcell = sW2 + ks*1152 + lane*36;
            #pragma unroll
            for (int jp = 0; jp < 4; jp++){
                float4 w = *(const float4*)(wcell + (((wn*4+jp) ^ swz) << 2));
                mma8(acc2[0][jp*2],   a0, __float_as_uint(w.x), __float_as_uint(w.y));
                mma8(acc2[1][jp*2],   a1, __float_as_uint(w.x), __float_as_uint(w.y));
                mma8(acc2[0][jp*2+1], a0, __float_as_uint(w.z), __float_as_uint(w.w));
                mma8(acc2[1][jp*2+1], a1, __float_as_uint(w.z), __float_as_uint(w.w));
            }
        }

        // ===== epilogue 2: segment-max(acc2) + b2 -> out (atomics) =====
        #pragma unroll
        for (int mt = 0; mt < 2; mt++)
            #pragma unroll
            for (int qr = 0; qr < 2; qr++){
                int r = wm*32 + mt*16 + qr*8 + gid;
                int g = sSB[par*128 + r];
                unsigned mg = __match_any_sync(0xffffffffu, g);
                unsigned mask = mg & (0x11111111u << tig);
                bool lead = (lane == (int)(__ffs(mask) - 1));
                #pragma unroll
                for (int nt = 0; nt < 8; nt++)
                    #pragma unroll
                    for (int qc = 0; qc < 2; qc++){
                        float v = acc2[mt][nt][qr*2+qc];
                        int fi = __float_as_int(v);
                        int key = fi ^ ((fi >> 31) & 0x7fffffff);
                        int m = __reduce_max_sync(mask, key);
                        if (lead && g >= 0){
                            int c = wn*64 + nt*8 + tig*2 + qc;
                            m ^= (m >> 31) & 0x7fffffff;
                            atomicMaxF(&out[g*DH + c], __int_as_float(m) + sB2[c]);
                        }
                    }
            }
        __syncthreads();   // (3) all H reads done

        if (hasNext) stA(pre, sBuf, sSB, 1 - par, TB, lkb, lhalf, lr);
        __syncthreads();   // (4) next A ready
    }
}

// ---------------------------------------------------------------------------
extern "C" void kernel_launch(void* const* d_in, const int* in_sizes, int n_in,
                              void* d_out, int out_size){
    const float* x     = (const float*)d_in[0];
    const float* pos   = (const float*)d_in[1];
    const int*   batch = (const int*)  d_in[2];
    const float* lf    = (const float*)d_in[3];
    const float* W1    = (const float*)d_in[4];
    const float* b1    = (const float*)d_in[5];
    const float* W2    = (const float*)d_in[6];
    const float* b2    = (const float*)d_in[7];
    float* out = (float*)d_out;
    int n = in_sizes[2];

    cudaFuncSetAttribute(k_main, cudaFuncAttributeMaxDynamicSharedMemorySize, SMEM_BYTES);

    k_init<<<32, 256>>>(out, out_size);
    int nb = (n + 255) / 256;
    k_com<<<nb, 256>>>(pos, batch, n);
    k_amin<<<nb, 256>>>(pos, batch, n);
    k_wprep<<<100, 256>>>(W1, W2);
    k_prep<<<NB, DH>>>(x, pos, batch, lf, W1, b1, out, out_size, n);
    k_main<<<148, 256, SMEM_BYTES>>>(x, pos, batch, b2, out, n);
}

// round 6
// speedup vs baseline: 1.0906x; 1.0906x over previous
#include <cuda_runtime.h>
#include <cstdint>

#define NB 64
#define DIN 64
#define DH 128
#define KA 72
#define TM 128

#define SW1_STRIDE 136
#define SW2_STRIDE 136
#define SA_STRIDE  76
#define SH_STRIDE  132

// float offsets in dynamic smem
#define OFF_W2 9792          // sW1: 72*136 = 9792
#define OFF_A  27200         // sW2: 128*136 = 17408
#define OFF_H  36928         // sA:  128*76  = 9728
#define OFF_B  53824         // sH:  128*132 = 16896 ; sB: 2*128 ints
#define OFF_B2 54080         // b2: 128 floats
#define SMEM_FLOATS 54208
#define SMEM_BYTES (SMEM_FLOATS*4)

#define CA_GRID 592          // 148 SMs * 4 blocks, all co-resident

__device__ float g_psum[NB*4];
__device__ unsigned long long g_amin[NB];
__device__ unsigned g_bar;
__device__ __align__(16) float g_cg[NB*DH];
__device__ __align__(16) float g_W1e[KA*DH];
__device__ __align__(16) float g_W2e[DH*DH];

__device__ __forceinline__ unsigned f2tf(float x){
    unsigned u; asm("cvt.rna.tf32.f32 %0, %1;" : "=r"(u) : "f"(x)); return u;
}
__device__ __forceinline__ uint32_t s2u(const void* p){
    uint32_t a; asm("{ .reg .u64 t; cvta.to.shared.u64 t, %1; cvt.u32.u64 %0, t; }" : "=r"(a) : "l"(p)); return a;
}
__device__ __forceinline__ void atomicMaxF(float* a, float v){
    if (v >= 0.f) atomicMax((int*)a, __float_as_int(v));
    else          atomicMin((unsigned int*)a, __float_as_uint(v));
}
__device__ __forceinline__ void mma8(float (&c)[4], const unsigned (&a)[4], unsigned b0, unsigned b1){
    asm volatile("mma.sync.aligned.m16n8k8.row.col.f32.tf32.tf32.f32 "
        "{%0,%1,%2,%3}, {%4,%5,%6,%7}, {%8,%9}, {%0,%1,%2,%3};\n"
        : "+f"(c[0]), "+f"(c[1]), "+f"(c[2]), "+f"(c[3])
        : "r"(a[0]), "r"(a[1]), "r"(a[2]), "r"(a[3]), "r"(b0), "r"(b1));
}

// ---------------------------------------------------------------------------
// launch 0: init + weight prep (tf32 RNA-rounded, canonical [k*DH+c] layout)
__global__ void k_init(const float* __restrict__ W1, const float* __restrict__ W2,
                       float* out, int out_size){
    int i = blockIdx.x*blockDim.x + threadIdx.x;
    if (i < NB*4) g_psum[i] = 0.f;
    if (i < NB)   g_amin[i] = 0xFFFFFFFFFFFFFFFFULL;
    if (i == 0)   g_bar = 0u;
    if (i < NB*DH && i < out_size) out[i] = __int_as_float(0xff800000);
    if (i < KA*DH){
        int k = i >> 7, c = i & 127;
        float v = 0.f;
        if (k < DIN)          v = W1[(DIN+k)*DH + c];
        else if (k < DIN+3)   v = W1[(2*DIN + (k-DIN))*DH + c];
        g_W1e[i] = __uint_as_float(f2tf(v));
    } else if (i < KA*DH + DH*DH){
        int j = i - KA*DH;
        g_W2e[j] = __uint_as_float(f2tf(W2[j]));
    }
}

// launch 1: fused COM + argmin with device-wide spin barrier (all blocks resident)
__global__ __launch_bounds__(256, 4) void k_comamin(
    const float* __restrict__ pos, const int* __restrict__ batch, int n){
    const int stride = CA_GRID*256;
    const int base = blockIdx.x*256 + threadIdx.x;
    const int trips = (n + stride - 1) / stride;

    // phase 1: COM partial sums
    for (int j = 0; j < trips; j++){
        int i = base + j*stride;
        int b = -1; float px=0.f, py=0.f, pz=0.f, pc=0.f;
        if (i < n){ b = batch[i]; px = pos[3*i]; py = pos[3*i+1]; pz = pos[3*i+2]; pc = 1.f; }
        int b0 = __shfl_sync(0xffffffffu, b, 0);
        bool uni = __all_sync(0xffffffffu, b == b0);
        if (uni){
            #pragma unroll
            for (int o = 16; o; o >>= 1){
                px += __shfl_down_sync(0xffffffffu, px, o);
                py += __shfl_down_sync(0xffffffffu, py, o);
                pz += __shfl_down_sync(0xffffffffu, pz, o);
                pc += __shfl_down_sync(0xffffffffu, pc, o);
            }
            if ((threadIdx.x & 31) == 0 && b0 >= 0){
                atomicAdd(&g_psum[b0*4+0], px); atomicAdd(&g_psum[b0*4+1], py);
                atomicAdd(&g_psum[b0*4+2], pz); atomicAdd(&g_psum[b0*4+3], pc);
            }
        } else if (b >= 0){
            atomicAdd(&g_psum[b*4+0], px); atomicAdd(&g_psum[b*4+1], py);
            atomicAdd(&g_psum[b*4+2], pz); atomicAdd(&g_psum[b*4+3], pc);
        }
    }

    // device-wide barrier (all CA_GRID blocks are co-resident)
    __threadfence();
    __syncthreads();
    if (threadIdx.x == 0){
        atomicAdd(&g_bar, 1u);
        while (atomicAdd(&g_bar, 0u) < (unsigned)CA_GRID) {}
    }
    __syncthreads();
    __threadfence();

    // phase 2: argmin dist-to-COM (packed key => first-occurrence semantics)
    for (int j = 0; j < trips; j++){
        int i = base + j*stride;
        int b = -1; unsigned long long key = 0xFFFFFFFFFFFFFFFFULL;
        if (i < n){
            b = batch[i];
            float cnt = fmaxf(g_psum[b*4+3], 1.f);
            float inv = 1.f / cnt;
            float dx = pos[3*i]   - g_psum[b*4+0]*inv;
            float dy = pos[3*i+1] - g_psum[b*4+1]*inv;
            float dz = pos[3*i+2] - g_psum[b*4+2]*inv;
            float d2 = dx*dx + dy*dy + dz*dz;
            key = ((unsigned long long)__float_as_uint(d2) << 32) | (unsigned)i;
        }
        int b0 = __shfl_sync(0xffffffffu, b, 0);
        bool uni = __all_sync(0xffffffffu, b == b0);
        if (uni){
            #pragma unroll
            for (int o = 16; o; o >>= 1){
                unsigned long long k2 = __shfl_down_sync(0xffffffffu, key, o);
                if (k2 < key) key = k2;
            }
            if ((threadIdx.x & 31) == 0 && b0 >= 0) atomicMin(&g_amin[b0], key);
        } else if (b >= 0){
            atomicMin(&g_amin[b], key);
        }
    }
}

// launch 2: per-graph bias cg + aux outputs
__global__ void k_prep(const float* __restrict__ x, const float* __restrict__ pos,
                       const int* __restrict__ batch, const float* __restrict__ lf,
                       const float* __restrict__ W1, const float* __restrict__ b1,
                       float* out, int out_size, int n){
    int g = blockIdx.x, c = threadIdx.x;
    __shared__ float sxd[DIN];
    __shared__ float sp3[3];
    __shared__ int sidx;
    if (c == 0){
        int id = (int)(unsigned)(g_amin[g] & 0xFFFFFFFFULL);
        if (id > n-1) id = n-1;
        sidx = id;
    }
    __syncthreads();
    int idx = sidx;
    if (c < DIN) sxd[c] = x[(size_t)idx*DIN + c];
    if (c < 3)   sp3[c] = pos[idx*3 + c];
    __syncthreads();
    float acc = b1[c];
    #pragma unroll 8
    for (int k = 0; k < DIN; k++)
        acc += sxd[k] * (W1[k*DH + c] - W1[(DIN+k)*DH + c]);
    #pragma unroll
    for (int j = 0; j < 3; j++)
        acc -= sp3[j] * W1[(2*DIN+j)*DH + c];
    g_cg[g*DH + c] = acc;

    if (out_size >= NB*DH + NB*3 + NB + NB*9){
        if (c < 3)  out[NB*DH + g*3 + c] = pos[idx*3 + c];
        if (c == 3) out[NB*DH + NB*3 + g] = (float)batch[idx];
        if (c < 9)  out[NB*DH + NB*3 + NB + g*9 + c] = lf[(size_t)idx*9 + c];
    }
}

// ---------------------------------------------------------------------------
// launch 3: main fused kernel (profiled)
__device__ __forceinline__ void issue_load(float* sm, uint32_t sA_u,
        const float* __restrict__ x, const float* __restrict__ pos,
        const int* __restrict__ batch, int n, int base, int slot, int tid)
{
    #pragma unroll
    for (int rep = 0; rep < 8; rep++){
        int i = tid + rep*256;
        int r = i >> 4, c4 = i & 15;
        int row = base + r;
        uint32_t dst = sA_u + (uint32_t)(r*SA_STRIDE + c4*4)*4u;
        const float* src = x + (size_t)(row < n ? row : 0)*DIN + c4*4;
        unsigned pb = (row < n) ? 16u : 0u;
        asm volatile("cp.async.cg.shared.global [%0], [%1], 16, %2;\n"
                     :: "r"(dst), "l"(src), "r"(pb) : "memory");
    }
    asm volatile("cp.async.commit_group;\n" ::: "memory");
    if (tid < TM){
        int row = base + tid;
        float* d = sm + OFF_A + tid*SA_STRIDE;
        int g = -1; float p0=0.f, p1=0.f, p2=0.f;
        if (row < n){ p0 = pos[3*row]; p1 = pos[3*row+1]; p2 = pos[3*row+2]; g = batch[row]; }
        d[64] = p0; d[65] = p1; d[66] = p2;
        ((int*)(sm + OFF_B))[slot*128 + tid] = g;
    }
}

__global__ __launch_bounds__(256, 1)
void k_main(const float* __restrict__ x, const float* __restrict__ pos,
            const int* __restrict__ batch, const float* __restrict__ b2,
            float* __restrict__ out, int n)
{
    extern __shared__ float sm[];
    float* sW1 = sm;
    float* sW2 = sm + OFF_W2;
    float* sA  = sm + OFF_A;
    float* sH  = sm + OFF_H;
    float* sB2 = sm + OFF_B2;

    const int tid = threadIdx.x, warp = tid >> 5, lane = tid & 31;
    const int gid = lane >> 2, tig = lane & 3;
    const int wm = warp >> 1, wn = warp & 1;
    const int m0 = wm*32, n0 = wn*64;
    const int numTiles = (n + TM - 1) / TM;
    const uint32_t sA_u = s2u(sA);

    // weights + b2 to smem; zero pad cols 67..71 of sA once
    for (int i = tid; i < KA*DH; i += 256){ int k = i >> 7, c = i & 127; sW1[k*SW1_STRIDE + c] = g_W1e[i]; }
    for (int i = tid; i < DH*DH; i += 256){ int k = i >> 7, c = i & 127; sW2[k*SW2_STRIDE + c] = g_W2e[i]; }
    if (tid < DH) sB2[tid] = b2[tid];
    if (tid < TM){
        float* d = sA + tid*SA_STRIDE;
        d[67] = d[68] = d[69] = d[70] = d[71] = 0.f;
    }

    const int t0 = blockIdx.x;
    if (t0 < numTiles) issue_load(sm, sA_u, x, pos, batch, n, t0*TM, 0, tid);
    asm volatile("cp.async.wait_group 0;\n" ::: "memory");
    __syncthreads();

    float acc[2][8][4];
    int it = 0;
    for (int t = t0; t < numTiles; t += 148, it++){
        const int par = it & 1;
        const int tn = t + 148;
        const int* sBc = (const int*)(sm + OFF_B) + par*128;

        // ===== layer 1: acc = A @ W1 =====
        #pragma unroll
        for (int mt = 0; mt < 2; mt++)
            #pragma unroll
            for (int nt = 0; nt < 8; nt++)
                #pragma unroll
                for (int q = 0; q < 4; q++) acc[mt][nt][q] = 0.f;

        #pragma unroll
        for (int ks = 0; ks < 9; ks++){
            int kk = ks * 8;
            unsigned a[2][4];
            #pragma unroll
            for (int mt = 0; mt < 2; mt++){
                const float* ap = sA + (m0 + mt*16 + gid)*SA_STRIDE + kk + tig;
                a[mt][0] = __float_as_uint(ap[0]);
                a[mt][1] = __float_as_uint(ap[8*SA_STRIDE]);
                a[mt][2] = __float_as_uint(ap[4]);
                a[mt][3] = __float_as_uint(ap[8*SA_STRIDE + 4]);
            }
            #pragma unroll
            for (int nt = 0; nt < 8; nt++){
                const float* bp = sW1 + (kk + tig)*SW1_STRIDE + n0 + nt*8 + gid;
                unsigned b0 = __float_as_uint(bp[0]);
                unsigned b1r = __float_as_uint(bp[4*SW1_STRIDE]);
                mma8(acc[0][nt], a[0], b0, b1r);
                mma8(acc[1][nt], a[1], b0, b1r);
            }
        }
        __syncthreads();   // (1) sA reads done

        // prefetch next tile into sA (hidden under epi1 + L2 + epi2)
        if (tn < numTiles) issue_load(sm, sA_u, x, pos, batch, n, tn*TM, 1 - par, tid);

        // ===== epilogue 1: h = relu(acc + cg[g]) -> sH (RNA tf32) =====
        #pragma unroll
        for (int mt = 0; mt < 2; mt++){
            int r0 = m0 + mt*16 + gid, r1 = r0 + 8;
            int g0 = sBc[r0], g1 = sBc[r1];
            const float2* cg0 = (const float2*)(g_cg + (size_t)(g0 < 0 ? 0 : g0)*DH);
            const float2* cg1 = (const float2*)(g_cg + (size_t)(g1 < 0 ? 0 : g1)*DH);
            #pragma unroll
            for (int nt = 0; nt < 8; nt++){
                int c0 = n0 + nt*8 + tig*2;
                float2 cA = __ldg(&cg0[c0 >> 1]);
                float2 cB = __ldg(&cg1[c0 >> 1]);
                float2 h0, h1;
                h0.x = __uint_as_float(f2tf(fmaxf(acc[mt][nt][0] + cA.x, 0.f)));
                h0.y = __uint_as_float(f2tf(fmaxf(acc[mt][nt][1] + cA.y, 0.f)));
                h1.x = __uint_as_float(f2tf(fmaxf(acc[mt][nt][2] + cB.x, 0.f)));
                h1.y = __uint_as_float(f2tf(fmaxf(acc[mt][nt][3] + cB.y, 0.f)));
                *(float2*)(sH + r0*SH_STRIDE + c0) = h0;
                *(float2*)(sH + r1*SH_STRIDE + c0) = h1;
            }
        }
        __syncthreads();   // (2) sH ready

        // ===== layer 2: acc = H @ W2 =====
        #pragma unroll
        for (int mt = 0; mt < 2; mt++)
            #pragma unroll
            for (int nt = 0; nt < 8; nt++)
                #pragma unroll
                for (int q = 0; q < 4; q++) acc[mt][nt][q] = 0.f;

        #pragma unroll
        for (int ks = 0; ks < 16; ks++){
            int kk = ks * 8;
            unsigned a[2][4];
            #pragma unroll
            for (int mt = 0; mt < 2; mt++){
                const float* ap = sH + (m0 + mt*16 + gid)*SH_STRIDE + kk + tig;
                a[mt][0] = __float_as_uint(ap[0]);
                a[mt][1] = __float_as_uint(ap[8*SH_STRIDE]);
                a[mt][2] = __float_as_uint(ap[4]);
                a[mt][3] = __float_as_uint(ap[8*SH_STRIDE + 4]);
            }
            #pragma unroll
            for (int nt = 0; nt < 8; nt++){
                const float* bp = sW2 + (kk + tig)*SW2_STRIDE + n0 + nt*8 + gid;
                unsigned b0 = __float_as_uint(bp[0]);
                unsigned b1r = __float_as_uint(bp[4*SW2_STRIDE]);
                mma8(acc[0][nt], a[0], b0, b1r);
                mma8(acc[1][nt], a[1], b0, b1r);
            }
        }

        // ===== epilogue 2: segment-max from registers -> atomics =====
        #pragma unroll
        for (int mt = 0; mt < 2; mt++)
            #pragma unroll
            for (int qr = 0; qr < 2; qr++){
                int r = m0 + mt*16 + qr*8 + gid;
                int g = sBc[r];
                unsigned mg = __match_any_sync(0xffffffffu, g);
                unsigned mask = mg & (0x11111111u << tig);
                bool lead = (lane == (int)(__ffs(mask) - 1));
                #pragma unroll
                for (int nt = 0; nt < 8; nt++)
                    #pragma unroll
                    for (int qc = 0; qc < 2; qc++){
                        int fi = __float_as_int(acc[mt][nt][qr*2+qc]);
                        int key = fi ^ ((fi >> 31) & 0x7fffffff);
                        int m = __reduce_max_sync(mask, key);
                        if (lead && g >= 0){
                            int c = n0 + nt*8 + tig*2 + qc;
                            m ^= (m >> 31) & 0x7fffffff;
                            atomicMaxF(&out[g*DH + c], __int_as_float(m) + sB2[c]);
                        }
                    }
            }

        asm volatile("cp.async.wait_group 0;\n" ::: "memory");
        __syncthreads();   // (3) next sA ready, sH reads done
    }
}

// ---------------------------------------------------------------------------
extern "C" void kernel_launch(void* const* d_in, const int* in_sizes, int n_in,
                              void* d_out, int out_size){
    const float* x     = (const float*)d_in[0];
    const float* pos   = (const float*)d_in[1];
    const int*   batch = (const int*)  d_in[2];
    const float* lf    = (const float*)d_in[3];
    const float* W1    = (const float*)d_in[4];
    const float* b1    = (const float*)d_in[5];
    const float* W2    = (const float*)d_in[6];
    const float* b2    = (const float*)d_in[7];
    float* out = (float*)d_out;
    int n = in_sizes[2];

    cudaFuncSetAttribute(k_main, cudaFuncAttributeMaxDynamicSharedMemorySize, SMEM_BYTES);

    k_init<<<104, 256>>>(W1, W2, out, out_size);
    k_comamin<<<CA_GRID, 256>>>(pos, batch, n);
    k_prep<<<NB, DH>>>(x, pos, batch, lf, W1, b1, out, out_size, n);
    k_main<<<148, 256, SMEM_BYTES>>>(x, pos, batch, b2, out, n);
}

// round 8
// speedup vs baseline: 2.6804x; 2.4577x over previous
#include <cuda_runtime.h>
#include <cstdint>

#define NB 64
#define DIN 64
#define DH 128
#define TM 128

// dynamic smem float offsets
#define OFF_W1F 0            // sW1p: 36 pair-rows * 132 f2 = 9504 floats
#define OFF_W2F 9504         // sW2p: 64 * 132 f2 = 16896 floats
#define OFF_A   26400        // sA: 128*72 floats
#define OFF_H   35616        // sH: 128*136 floats
#define OFF_B2  53024        // b2: 128 floats
#define OFF_SB  53152        // batch ids: 2*128 ints
#define SMEM_FLOATS 53408
#define SMEM_BYTES (SMEM_FLOATS*4)

#define CA_GRID 592

__device__ float g_psum[NB*4];
__device__ unsigned long long g_amin[NB];
__device__ unsigned g_bar;
__device__ __align__(16) float g_cg[NB*DH];
__device__ __align__(16) float2 g_W1p[36*128];   // [ks*4+tig][col] pair=(k0,k0+1)
__device__ __align__(16) float2 g_W2p[64*128];

__device__ __forceinline__ unsigned f2tf(float x){
    unsigned u; asm("cvt.rna.tf32.f32 %0, %1;" : "=r"(u) : "f"(x)); return u;
}
__device__ __forceinline__ uint32_t s2u(const void* p){
    uint32_t a; asm("{ .reg .u64 t; cvta.to.shared.u64 t, %1; cvt.u32.u64 %0, t; }" : "=r"(a) : "l"(p)); return a;
}
__device__ __forceinline__ void atomicMaxF(float* a, float v){
    if (v >= 0.f) atomicMax((int*)a, __float_as_int(v));
    else          atomicMin((unsigned int*)a, __float_as_uint(v));
}
__device__ __forceinline__ void mma8(float (&c)[4], unsigned a0, unsigned a1, unsigned a2, unsigned a3,
                                     unsigned b0, unsigned b1){
    asm volatile("mma.sync.aligned.m16n8k8.row.col.f32.tf32.tf32.f32 "
        "{%0,%1,%2,%3}, {%4,%5,%6,%7}, {%8,%9}, {%0,%1,%2,%3};\n"
        : "+f"(c[0]), "+f"(c[1]), "+f"(c[2]), "+f"(c[3])
        : "r"(a0), "r"(a1), "r"(a2), "r"(a3), "r"(b0), "r"(b1));
}

// ---------------------------------------------------------------------------
// launch 0: init + pair-packed tf32 weights (K-permuted: pair (k0,k0+1) at (ks,tig))
__global__ void k_init(const float* __restrict__ W1, const float* __restrict__ W2,
                       float* out, int out_size){
    int i = blockIdx.x*blockDim.x + threadIdx.x;
    if (i < NB*4) g_psum[i] = 0.f;
    if (i < NB)   g_amin[i] = 0xFFFFFFFFFFFFFFFFULL;
    if (i == 0)   g_bar = 0u;
    if (i < NB*DH && i < out_size) out[i] = __int_as_float(0xff800000);

    if (i < 36*128){
        int pr = i >> 7, c = i & 127;
        int ks = pr >> 2, tig = pr & 3;
        int k0 = ks*8 + 2*tig;
        float v0 = 0.f, v1 = 0.f;
        // effective W1 row k: k<64 -> W1[64+k]; 64..66 -> W1[128+(k-64)]; else 0
        if (k0 < 64)       v0 = W1[(64+k0)*DH + c];
        else if (k0 < 67)  v0 = W1[(128 + (k0-64))*DH + c];
        int k1 = k0 + 1;
        if (k1 < 64)       v1 = W1[(64+k1)*DH + c];
        else if (k1 < 67)  v1 = W1[(128 + (k1-64))*DH + c];
        g_W1p[i] = make_float2(__uint_as_float(f2tf(v0)), __uint_as_float(f2tf(v1)));
    } else if (i < 36*128 + 64*128){
        int j = i - 36*128;
        int pr = j >> 7, c = j & 127;
        int ks = pr >> 2, tig = pr & 3;
        int k0 = ks*8 + 2*tig;
        g_W2p[j] = make_float2(__uint_as_float(f2tf(W2[k0*DH + c])),
                               __uint_as_float(f2tf(W2[(k0+1)*DH + c])));
    }
}

// launch 1: fused COM + argmin with device-wide spin barrier (592 blocks,
// 256 thr, <=32 regs, 0 smem -> 4 CTAs/SM co-resident guaranteed)
__global__ __launch_bounds__(256, 4) void k_comamin(
    const float* __restrict__ pos, const int* __restrict__ batch, int n){
    const int stride = CA_GRID*256;
    const int base = blockIdx.x*256 + threadIdx.x;
    const int trips = (n + stride - 1) / stride;

    for (int j = 0; j < trips; j++){
        int i = base + j*stride;
        int b = -1; float px=0.f, py=0.f, pz=0.f, pc=0.f;
        if (i < n){ b = batch[i]; px = pos[3*i]; py = pos[3*i+1]; pz = pos[3*i+2]; pc = 1.f; }
        int b0 = __shfl_sync(0xffffffffu, b, 0);
        bool uni = __all_sync(0xffffffffu, b == b0);
        if (uni){
            #pragma unroll
            for (int o = 16; o; o >>= 1){
                px += __shfl_down_sync(0xffffffffu, px, o);
                py += __shfl_down_sync(0xffffffffu, py, o);
                pz += __shfl_down_sync(0xffffffffu, pz, o);
                pc += __shfl_down_sync(0xffffffffu, pc, o);
            }
            if ((threadIdx.x & 31) == 0 && b0 >= 0){
                atomicAdd(&g_psum[b0*4+0], px); atomicAdd(&g_psum[b0*4+1], py);
                atomicAdd(&g_psum[b0*4+2], pz); atomicAdd(&g_psum[b0*4+3], pc);
            }
        } else if (b >= 0){
            atomicAdd(&g_psum[b*4+0], px); atomicAdd(&g_psum[b*4+1], py);
            atomicAdd(&g_psum[b*4+2], pz); atomicAdd(&g_psum[b*4+3], pc);
        }
    }

    __threadfence();
    __syncthreads();
    if (threadIdx.x == 0){
        atomicAdd(&g_bar, 1u);
        while (atomicAdd(&g_bar, 0u) < (unsigned)CA_GRID) __nanosleep(64);
    }
    __syncthreads();
    __threadfence();

    for (int j = 0; j < trips; j++){
        int i = base + j*stride;
        int b = -1; unsigned long long key = 0xFFFFFFFFFFFFFFFFULL;
        if (i < n){
            b = batch[i];
            float cnt = fmaxf(g_psum[b*4+3], 1.f);
            float inv = 1.f / cnt;
            float dx = pos[3*i]   - g_psum[b*4+0]*inv;
            float dy = pos[3*i+1] - g_psum[b*4+1]*inv;
            float dz = pos[3*i+2] - g_psum[b*4+2]*inv;
            float d2 = dx*dx + dy*dy + dz*dz;
            key = ((unsigned long long)__float_as_uint(d2) << 32) | (unsigned)i;
        }
        int b0 = __shfl_sync(0xffffffffu, b, 0);
        bool uni = __all_sync(0xffffffffu, b == b0);
        if (uni){
            #pragma unroll
            for (int o = 16; o; o >>= 1){
                unsigned long long k2 = __shfl_down_sync(0xffffffffu, key, o);
                if (k2 < key) key = k2;
            }
            if ((threadIdx.x & 31) == 0 && b0 >= 0) atomicMin(&g_amin[b0], key);
        } else if (b >= 0){
            atomicMin(&g_amin[b], key);
        }
    }
}

// launch 2: per-graph bias cg + aux outputs
__global__ void k_prep(const float* __restrict__ x, const float* __restrict__ pos,
                       const int* __restrict__ batch, const float* __restrict__ lf,
                       const float* __restrict__ W1, const float* __restrict__ b1,
                       float* out, int out_size, int n){
    int g = blockIdx.x, c = threadIdx.x;
    __shared__ float sxd[DIN];
    __shared__ float sp3[3];
    __shared__ int sidx;
    if (c == 0){
        int id = (int)(unsigned)(g_amin[g] & 0xFFFFFFFFULL);
        if (id > n-1) id = n-1;
        sidx = id;
    }
    __syncthreads();
    int idx = sidx;
    if (c < DIN) sxd[c] = x[(size_t)idx*DIN + c];
    if (c < 3)   sp3[c] = pos[idx*3 + c];
    __syncthreads();
    float acc = b1[c];
    #pragma unroll 8
    for (int k = 0; k < DIN; k++)
        acc += sxd[k] * (W1[k*DH + c] - W1[(DIN+k)*DH + c]);
    #pragma unroll
    for (int j = 0; j < 3; j++)
        acc -= sp3[j] * W1[(2*DIN+j)*DH + c];
    g_cg[g*DH + c] = acc;

    if (out_size >= NB*DH + NB*3 + NB + NB*9){
        if (c < 3)  out[NB*DH + g*3 + c] = pos[idx*3 + c];
        if (c == 3) out[NB*DH + NB*3 + g] = (float)batch[idx];
        if (c < 9)  out[NB*DH + NB*3 + NB + g*9 + c] = lf[(size_t)idx*9 + c];
    }
}

// ---------------------------------------------------------------------------
// launch 3: main fused kernel, 512 threads, warp tile 32x32
__device__ __forceinline__ void issue_load(float* sm, uint32_t sA_u,
        const float* __restrict__ x, const float* __restrict__ pos,
        const int* __restrict__ batch, int n, int base, int slot, int tid)
{
    #pragma unroll
    for (int rep = 0; rep < 4; rep++){
        int i = tid + rep*512;
        int r = i >> 4, c4 = i & 15;
        int row = base + r;
        uint32_t dst = sA_u + (uint32_t)(r*72 + c4*4)*4u;
        const float* src = x + (size_t)(row < n ? row : 0)*DIN + c4*4;
        unsigned pb = (row < n) ? 16u : 0u;
        asm volatile("cp.async.cg.shared.global [%0], [%1], 16, %2;\n"
                     :: "r"(dst), "l"(src), "r"(pb) : "memory");
    }
    asm volatile("cp.async.commit_group;\n" ::: "memory");
    if (tid < TM){
        int row = base + tid;
        float* d = sm + OFF_A + tid*72;
        int g = -1; float p0=0.f, p1=0.f, p2=0.f;
        if (row < n){ p0 = pos[3*row]; p1 = pos[3*row+1]; p2 = pos[3*row+2]; g = batch[row]; }
        d[64] = p0; d[65] = p1; d[66] = p2;
        ((int*)(sm + OFF_SB))[slot*128 + tid] = g;
    }
}

__global__ __launch_bounds__(512, 1)
void k_main(const float* __restrict__ x, const float* __restrict__ pos,
            const int* __restrict__ batch, const float* __restrict__ b2,
            float* __restrict__ out, int n)
{
    extern __shared__ float sm[];
    float2* sW1 = (float2*)(sm + OFF_W1F);   // [pr][col] stride 132 f2
    float2* sW2 = (float2*)(sm + OFF_W2F);
    float*  sA  = sm + OFF_A;                // [128][72]
    float*  sH  = sm + OFF_H;                // [128][136]
    float*  sB2 = sm + OFF_B2;

    const int tid = threadIdx.x, warp = tid >> 5, lane = tid & 31;
    const int gid = lane >> 2, tig = lane & 3;
    const int wm = warp >> 2, wn = warp & 3;
    const int m0 = wm*32, n0 = wn*32;
    const int numTiles = (n + TM - 1) / TM;
    const uint32_t sA_u = s2u(sA);

    // weights + b2 to smem (pair rows, stride 132 f2)
    for (int i = tid; i < 36*128; i += 512){
        int pr = i >> 7, c = i & 127;
        sW1[pr*132 + c] = g_W1p[i];
    }
    for (int i = tid; i < 64*128; i += 512){
        int pr = i >> 7, c = i & 127;
        sW2[pr*132 + c] = g_W2p[i];
    }
    if (tid < DH) sB2[tid] = b2[tid];
    if (tid < TM){   // zero pad cols 67..71 once
        float* d = sA + tid*72;
        d[67] = d[68] = d[69] = d[70] = d[71] = 0.f;
    }

    const int t0 = blockIdx.x;
    if (t0 < numTiles) issue_load(sm, sA_u, x, pos, batch, n, t0*TM, 0, tid);
    asm volatile("cp.async.wait_group 0;\n" ::: "memory");
    __syncthreads();

    float acc[2][4][4];
    int it = 0;
    for (int t = t0; t < numTiles; t += 148, it++){
        const int par = it & 1;
        const int tn = t + 148;
        const int* sBc = (const int*)(sm + OFF_SB) + par*128;

        // ===== layer 1: acc = A @ W1 =====
        #pragma unroll
        for (int mt = 0; mt < 2; mt++)
            #pragma unroll
            for (int nt = 0; nt < 4; nt++)
                #pragma unroll
                for (int q = 0; q < 4; q++) acc[mt][nt][q] = 0.f;

        #pragma unroll
        for (int ks = 0; ks < 9; ks++){
            const int kk = ks*8 + tig*2;
            float2 a[2][2];
            #pragma unroll
            for (int mt = 0; mt < 2; mt++){
                const float* ap = sA + (m0 + mt*16 + gid)*72 + kk;
                a[mt][0] = *(const float2*)ap;            // row r   : (a0,a2)
                a[mt][1] = *(const float2*)(ap + 8*72);   // row r+8 : (a1,a3)
            }
            const float2* wrow = sW1 + (ks*4 + tig)*132 + n0 + gid;
            #pragma unroll
            for (int nt = 0; nt < 4; nt++){
                float2 w = wrow[nt*8];
                #pragma unroll
                for (int mt = 0; mt < 2; mt++)
                    mma8(acc[mt][nt],
                         __float_as_uint(a[mt][0].x), __float_as_uint(a[mt][1].x),
                         __float_as_uint(a[mt][0].y), __float_as_uint(a[mt][1].y),
                         __float_as_uint(w.x), __float_as_uint(w.y));
            }
        }
        __syncthreads();   // (1) sA reads done

        // prefetch next tile into sA
        if (tn < numTiles) issue_load(sm, sA_u, x, pos, batch, n, tn*TM, 1 - par, tid);

        // ===== epilogue 1: h = relu(acc + cg[g]) -> sH (RNA tf32) =====
        #pragma unroll
        for (int mt = 0; mt < 2; mt++){
            int r0 = m0 + mt*16 + gid, r1 = r0 + 8;
            int g0 = sBc[r0], g1 = sBc[r1];
            const float2* cg0 = (const float2*)(g_cg + (size_t)(g0 < 0 ? 0 : g0)*DH);
            const float2* cg1 = (const float2*)(g_cg + (size_t)(g1 < 0 ? 0 : g1)*DH);
            #pragma unroll
            for (int nt = 0; nt < 4; nt++){
                int c0 = n0 + nt*8 + tig*2;
                float2 cA = __ldg(&cg0[c0 >> 1]);
                float2 cB = __ldg(&cg1[c0 >> 1]);
                float2 h0, h1;
                h0.x = __uint_as_float(f2tf(fmaxf(acc[mt][nt][0] + cA.x, 0.f)));
                h0.y = __uint_as_float(f2tf(fmaxf(acc[mt][nt][1] + cA.y, 0.f)));
                h1.x = __uint_as_float(f2tf(fmaxf(acc[mt][nt][2] + cB.x, 0.f)));
                h1.y = __uint_as_float(f2tf(fmaxf(acc[mt][nt][3] + cB.y, 0.f)));
                *(float2*)(sH + r0*136 + c0) = h0;
                *(float2*)(sH + r1*136 + c0) = h1;
            }
        }
        __syncthreads();   // (2) sH ready

        // ===== layer 2: acc = H @ W2 =====
        #pragma unroll
        for (int mt = 0; mt < 2; mt++)
            #pragma unroll
            for (int nt = 0; nt < 4; nt++)
                #pragma unroll
                for (int q = 0; q < 4; q++) acc[mt][nt][q] = 0.f;

        #pragma unroll
        for (int ks = 0; ks < 16; ks++){
            const int kk = ks*8 + tig*2;
            float2 a[2][2];
            #pragma unroll
            for (int mt = 0; mt < 2; mt++){
                const float* ap = sH + (m0 + mt*16 + gid)*136 + kk;
                a[mt][0] = *(const float2*)ap;
                a[mt][1] = *(const float2*)(ap + 8*136);
            }
            const float2* wrow = sW2 + (ks*4 + tig)*132 + n0 + gid;
            #pragma unroll
            for (int nt = 0; nt < 4; nt++){
                float2 w = wrow[nt*8];
                #pragma unroll
                for (int mt = 0; mt < 2; mt++)
                    mma8(acc[mt][nt],
                         __float_as_uint(a[mt][0].x), __float_as_uint(a[mt][1].x),
                         __float_as_uint(a[mt][0].y), __float_as_uint(a[mt][1].y),
                         __float_as_uint(w.x), __float_as_uint(w.y));
            }
        }
        __syncthreads();   // (3) sH reads done, safe to overwrite

        // ===== store raw msg tile into sH =====
        #pragma unroll
        for (int mt = 0; mt < 2; mt++){
            int r0 = m0 + mt*16 + gid, r1 = r0 + 8;
            #pragma unroll
            for (int nt = 0; nt < 4; nt++){
                int c0 = n0 + nt*8 + tig*2;
                *(float2*)(sH + r0*136 + c0) = make_float2(acc[mt][nt][0], acc[mt][nt][1]);
                *(float2*)(sH + r1*136 + c0) = make_float2(acc[mt][nt][2], acc[mt][nt][3]);
            }
        }
        __syncthreads();   // (4) msg tile ready

        // ===== segment-max column scan (4 threads/col, 32 rows each) =====
        {
            int col = tid >> 2;
            int rs  = (tid & 3) * 32;
            float b2c = sB2[col];
            float runmax = __int_as_float(0xff800000);
            int gcur = -1;
            #pragma unroll 4
            for (int r = rs; r < rs + 32; r++){
                int g = sBc[r];
                if (g != gcur){
                    if (gcur >= 0) atomicMaxF(&out[gcur*DH + col], runmax + b2c);
                    gcur = g; runmax = __int_as_float(0xff800000);
                }
                runmax = fmaxf(runmax, sH[r*136 + col]);
            }
            if (gcur >= 0) atomicMaxF(&out[gcur*DH + col], runmax + b2c);
        }

        asm volatile("cp.async.wait_group 0;\n" ::: "memory");
        __syncthreads();   // (5) next sA ready, scan reads done
    }
}

// ---------------------------------------------------------------------------
extern "C" void kernel_launch(void* const* d_in, const int* in_sizes, int n_in,
                              void* d_out, int out_size){
    const float* x     = (const float*)d_in[0];
    const float* pos   = (const float*)d_in[1];
    const int*   batch = (const int*)  d_in[2];
    const float* lf    = (const float*)d_in[3];
    const float* W1    = (const float*)d_in[4];
    const float* b1    = (const float*)d_in[5];
    const float* W2    = (const float*)d_in[6];
    const float* b2    = (const float*)d_in[7];
    float* out = (float*)d_out;
    int n = in_sizes[2];

    cudaFuncSetAttribute(k_main, cudaFuncAttributeMaxDynamicSharedMemorySize, SMEM_BYTES);

    k_init<<<104, 256>>>(W1, W2, out, out_size);
    k_comamin<<<CA_GRID, 256>>>(pos, batch, n);
    k_prep<<<NB, DH>>>(x, pos, batch, lf, W1, b1, out, out_size, n);
    k_main<<<148, 512, SMEM_BYTES>>>(x, pos, batch, b2, out, n);
}

// round 11
// speedup vs baseline: 2.8872x; 1.0772x over previous
#include <cuda_runtime.h>
#include <cstdint>

#define NB 64
#define DIN 64
#define DH 128
#define TM 128

// byte offsets in dynamic smem (all 16B aligned)
#define OFFB_W1 0            // 5ds*128col*4tig float4 = 40960 B
#define OFFB_W2 40960        // 8ds*128col*4tig float4 = 65536 B
#define OFFB_A  106496       // 128 rows * 320 B = 40960 B
#define OFFB_H  147456       // 128 rows * 576 B = 73728 B
#define OFFB_B2 221184       // 128 floats
#define OFFB_SB 221696       // 2*128 ints
#define SMEM_BYTES 222720

#define CA_GRID 592

__device__ float g_psum[NB*4];
__device__ unsigned long long g_amin[NB];
__device__ unsigned g_bar;
__device__ __align__(16) float g_cg[NB*DH];
__device__ __align__(16) float4 g_W1p[5*128*4];   // [ds*512 + col*4 + tig]
__device__ __align__(16) float4 g_W2p[8*128*4];

__device__ __forceinline__ unsigned f2tf(float x){
    unsigned u; asm("cvt.rna.tf32.f32 %0, %1;" : "=r"(u) : "f"(x)); return u;
}
__device__ __forceinline__ float f2tff(float x){ return __uint_as_float(f2tf(x)); }
__device__ __forceinline__ uint32_t s2u(const void* p){
    uint32_t a; asm("{ .reg .u64 t; cvta.to.shared.u64 t, %1; cvt.u32.u64 %0, t; }" : "=r"(a) : "l"(p)); return a;
}
__device__ __forceinline__ void atomicMaxF(float* a, float v){
    if (v >= 0.f) atomicMax((int*)a, __float_as_int(v));
    else          atomicMin((unsigned int*)a, __float_as_uint(v));
}
__device__ __forceinline__ void mma8(float (&c)[4], unsigned a0, unsigned a1, unsigned a2, unsigned a3,
                                     unsigned b0, unsigned b1){
    asm volatile("mma.sync.aligned.m16n8k8.row.col.f32.tf32.tf32.f32 "
        "{%0,%1,%2,%3}, {%4,%5,%6,%7}, {%8,%9}, {%0,%1,%2,%3};\n"
        : "+f"(c[0]), "+f"(c[1]), "+f"(c[2]), "+f"(c[3])
        : "r"(a0), "r"(a1), "r"(a2), "r"(a3), "r"(b0), "r"(b1));
}
#define U(x) __float_as_uint(x)

// ---------------------------------------------------------------------------
// launch 0: init + pack weights into 16B-cell layouts
__global__ void k_init(const float* __restrict__ W1, const float* __restrict__ W2,
                       float* out, int out_size){
    int i = blockIdx.x*blockDim.x + threadIdx.x;
    if (i < NB*4) g_psum[i] = 0.f;
    if (i < NB)   g_amin[i] = 0xFFFFFFFFFFFFFFFFULL;
    if (i == 0)   g_bar = 0u;
    if (i < NB*DH && i < out_size) out[i] = __int_as_float(0xff800000);

    if (i < 5*128*4){
        // W1 pack: cell (ds, col, tig) = effective-W1 rows for x-chunk ch = ds*4+tig
        int ds = i >> 9, col = (i >> 2) & 127, tig = i & 3;
        int ch = ds*4 + tig;
        float v[4];
        #pragma unroll
        for (int j = 0; j < 4; j++){
            float w = 0.f;
            if (ch < 16){ int xc = ch*4 + j; w = W1[(DIN + xc)*DH + col]; }
            else if (ch == 16 && j < 3){ w = W1[(2*DIN + j)*DH + col]; }
            v[j] = f2tff(w);
        }
        g_W1p[i] = make_float4(v[0], v[1], v[2], v[3]);
    } else if (i < 5*128*4 + 8*128*4){
        int q = i - 5*128*4;
        int ds = q >> 9, col = (q >> 2) & 127, tig = q & 3;
        float v[4];
        #pragma unroll
        for (int j = 0; j < 4; j++){
            int kh = 32*(ds >> 1) + 16*(ds & 1) + 8*(j >> 1) + tig*2 + (j & 1);
            v[j] = f2tff(W2[kh*DH + col]);
        }
        g_W2p[q] = make_float4(v[0], v[1], v[2], v[3]);
    }
}

// launch 1: fused COM + argmin, device-wide spin barrier (4 CTA/SM guaranteed)
__global__ __launch_bounds__(256, 4) void k_comamin(
    const float* __restrict__ pos, const int* __restrict__ batch, int n){
    const int stride = CA_GRID*256;
    const int base = blockIdx.x*256 + threadIdx.x;
    const int trips = (n + stride - 1) / stride;

    for (int j = 0; j < trips; j++){
        int i = base + j*stride;
        int b = -1; float px=0.f, py=0.f, pz=0.f, pc=0.f;
        if (i < n){ b = batch[i]; px = pos[3*i]; py = pos[3*i+1]; pz = pos[3*i+2]; pc = 1.f; }
        int b0 = __shfl_sync(0xffffffffu, b, 0);
        bool uni = __all_sync(0xffffffffu, b == b0);
        if (uni){
            #pragma unroll
            for (int o = 16; o; o >>= 1){
                px += __shfl_down_sync(0xffffffffu, px, o);
                py += __shfl_down_sync(0xffffffffu, py, o);
                pz += __shfl_down_sync(0xffffffffu, pz, o);
                pc += __shfl_down_sync(0xffffffffu, pc, o);
            }
            if ((threadIdx.x & 31) == 0 && b0 >= 0){
                atomicAdd(&g_psum[b0*4+0], px); atomicAdd(&g_psum[b0*4+1], py);
                atomicAdd(&g_psum[b0*4+2], pz); atomicAdd(&g_psum[b0*4+3], pc);
            }
        } else if (b >= 0){
            atomicAdd(&g_psum[b*4+0], px); atomicAdd(&g_psum[b*4+1], py);
            atomicAdd(&g_psum[b*4+2], pz); atomicAdd(&g_psum[b*4+3], pc);
        }
    }

    __threadfence();
    __syncthreads();
    if (threadIdx.x == 0){
        atomicAdd(&g_bar, 1u);
        while (atomicAdd(&g_bar, 0u) < (unsigned)CA_GRID) __nanosleep(64);
    }
    __syncthreads();
    __threadfence();

    for (int j = 0; j < trips; j++){
        int i = base + j*stride;
        int b = -1; unsigned long long key = 0xFFFFFFFFFFFFFFFFULL;
        if (i < n){
            b = batch[i];
            float cnt = fmaxf(g_psum[b*4+3], 1.f);
            float inv = 1.f / cnt;
            float dx = pos[3*i]   - g_psum[b*4+0]*inv;
            float dy = pos[3*i+1] - g_psum[b*4+1]*inv;
            float dz = pos[3*i+2] - g_psum[b*4+2]*inv;
            float d2 = dx*dx + dy*dy + dz*dz;
            key = ((unsigned long long)__float_as_uint(d2) << 32) | (unsigned)i;
        }
        int b0 = __shfl_sync(0xffffffffu, b, 0);
        bool uni = __all_sync(0xffffffffu, b == b0);
        if (uni){
            #pragma unroll
            for (int o = 16; o; o >>= 1){
                unsigned long long k2 = __shfl_down_sync(0xffffffffu, key, o);
                if (k2 < key) key = k2;
            }
            if ((threadIdx.x & 31) == 0 && b0 >= 0) atomicMin(&g_amin[b0], key);
        } else if (b >= 0){
            atomicMin(&g_amin[b], key);
        }
    }
}

// launch 2: per-graph bias cg + aux outputs
__global__ void k_prep(const float* __restrict__ x, const float* __restrict__ pos,
                       const int* __restrict__ batch, const float* __restrict__ lf,
                       const float* __restrict__ W1, const float* __restrict__ b1,
                       float* out, int out_size, int n){
    int g = blockIdx.x, c = threadIdx.x;
    __shared__ float sxd[DIN];
    __shared__ float sp3[3];
    __shared__ int sidx;
    if (c == 0){
        int id = (int)(unsigned)(g_amin[g] & 0xFFFFFFFFULL);
        if (id > n-1) id = n-1;
        sidx = id;
    }
    __syncthreads();
    int idx = sidx;
    if (c < DIN) sxd[c] = x[(size_t)idx*DIN + c];
    if (c < 3)   sp3[c] = pos[idx*3 + c];
    __syncthreads();
    float acc = b1[c];
    #pragma unroll 8
    for (int k = 0; k < DIN; k++)
        acc += sxd[k] * (W1[k*DH + c] - W1[(DIN+k)*DH + c]);
    #pragma unroll
    for (int j = 0; j < 3; j++)
        acc -= sp3[j] * W1[(2*DIN+j)*DH + c];
    g_cg[g*DH + c] = acc;

    if (out_size >= NB*DH + NB*3 + NB + NB*9){
        if (c < 3)  out[NB*DH + g*3 + c] = pos[idx*3 + c];
        if (c == 3) out[NB*DH + NB*3 + g] = (float)batch[idx];
        if (c < 9)  out[NB*DH + NB*3 + NB + g*9 + c] = lf[(size_t)idx*9 + c];
    }
}

// ---------------------------------------------------------------------------
__device__ __forceinline__ void issue_load(char* smem, uint32_t sA_u,
        const float* __restrict__ x, const float* __restrict__ pos,
        const int* __restrict__ batch, int n, int base, int slot, int tid)
{
    #pragma unroll
    for (int rep = 0; rep < 4; rep++){
        int i = tid + rep*512;
        int r = i >> 4, ch = i & 15;
        int row = base + r;
        uint32_t dst = sA_u + (uint32_t)(r*320 + ch*16);
        const float* src = x + (size_t)(row < n ? row : 0)*DIN + ch*4;
        unsigned pb = (row < n) ? 16u : 0u;
        asm volatile("cp.async.cg.shared.global [%0], [%1], 16, %2;\n"
                     :: "r"(dst), "l"(src), "r"(pb) : "memory");
    }
    asm volatile("cp.async.commit_group;\n" ::: "memory");
    if (tid < TM){
        int row = base + tid;
        float4 p = make_float4(0.f, 0.f, 0.f, 0.f);
        int g = -1;
        if (row < n){ p.x = pos[3*row]; p.y = pos[3*row+1]; p.z = pos[3*row+2]; g = batch[row]; }
        *(float4*)(smem + OFFB_A + tid*320 + 256) = p;
        ((int*)(smem + OFFB_SB))[slot*128 + tid] = g;
    }
}

__global__ __launch_bounds__(512, 1)
void k_main(const float* __restrict__ x, const float* __restrict__ pos,
            const int* __restrict__ batch, const float* __restrict__ b2,
            float* __restrict__ out, int n)
{
    extern __shared__ __align__(16) char smem[];
    const float4* sW1q = (const float4*)(smem + OFFB_W1);
    const float4* sW2q = (const float4*)(smem + OFFB_W2);
    const float4* sAq  = (const float4*)(smem + OFFB_A);
    float4*       sHq  = (float4*)(smem + OFFB_H);
    float*        sB2  = (float*)(smem + OFFB_B2);

    const int tid = threadIdx.x, lane = tid & 31, warp = tid >> 5;
    const int gid = lane >> 2, tig = lane & 3;
    const int wm = warp >> 2, wn = warp & 3;
    const int m0 = wm*32, n0 = wn*32;
    const int numTiles = (n + TM - 1) / TM;
    const uint32_t sA_u = s2u(smem + OFFB_A);

    // prologue: weights, b2, zero A pad cells (ch 17..19, never rewritten)
    {
        float4* w1 = (float4*)(smem + OFFB_W1);
        float4* w2 = (float4*)(smem + OFFB_W2);
        for (int i = tid; i < 5*128*4; i += 512) w1[i] = g_W1p[i];
        for (int i = tid; i < 8*128*4; i += 512) w2[i] = g_W2p[i];
        if (tid < DH) sB2[tid] = b2[tid];
        if (tid < TM){
            float4* z = (float4*)(smem + OFFB_A + tid*320 + 272);
            z[0] = z[1] = z[2] = make_float4(0.f,0.f,0.f,0.f);
        }
    }

    const int t0 = blockIdx.x;
    if (t0 < numTiles) issue_load(smem, sA_u, x, pos, batch, n, t0*TM, 0, tid);
    asm volatile("cp.async.wait_group 0;\n" ::: "memory");
    __syncthreads();

    float acc[2][4][4];
    int it = 0;
    for (int t = t0; t < numTiles; t += 148, it++){
        const int par = it & 1;
        const int tn = t + 148;
        const int* sBc = (const int*)(smem + OFFB_SB) + par*128;

        // ===== layer 1: acc = A @ W1 (5 double-k-steps) =====
        #pragma unroll
        for (int mt = 0; mt < 2; mt++)
            #pragma unroll
            for (int nt = 0; nt < 4; nt++)
                #pragma unroll
                for (int q = 0; q < 4; q++) acc[mt][nt][q] = 0.f;

        #pragma unroll
        for (int ds = 0; ds < 5; ds++){
            float4 a0[2], a1[2];
            #pragma unroll
            for (int mt = 0; mt < 2; mt++){
                int r = m0 + mt*16 + gid;
                a0[mt] = sAq[r*20 + ds*4 + tig];
                a1[mt] = sAq[(r+8)*20 + ds*4 + tig];
            }
            #pragma unroll
            for (int nt = 0; nt < 4; nt++){
                float4 w = sW1q[ds*512 + (n0 + nt*8 + gid)*4 + tig];
                #pragma unroll
                for (int mt = 0; mt < 2; mt++){
                    mma8(acc[mt][nt], U(a0[mt].x), U(a1[mt].x), U(a0[mt].y), U(a1[mt].y), U(w.x), U(w.y));
                    mma8(acc[mt][nt], U(a0[mt].z), U(a1[mt].z), U(a0[mt].w), U(a1[mt].w), U(w.z), U(w.w));
                }
            }
        }
        __syncthreads();   // (1) sA reads done

        // prefetch next tile into sA
        if (tn < numTiles) issue_load(smem, sA_u, x, pos, batch, n, tn*TM, 1 - par, tid);

        // ===== epilogue 1: h = relu(acc + cg[g]) -> sH packs (STS.128) =====
        #pragma unroll
        for (int mt = 0; mt < 2; mt++){
            int r0 = m0 + mt*16 + gid, r1 = r0 + 8;
            int g0 = sBc[r0], g1 = sBc[r1];
            const float2* cg0 = (const float2*)(g_cg + (size_t)(g0 < 0 ? 0 : g0)*DH);
            const float2* cg1 = (const float2*)(g_cg + (size_t)(g1 < 0 ? 0 : g1)*DH);
            float hv[4][4];
            #pragma unroll
            for (int nt = 0; nt < 4; nt++){
                int c0 = n0 + nt*8 + tig*2;
                float2 cA = __ldg(&cg0[c0 >> 1]);
                float2 cB = __ldg(&cg1[c0 >> 1]);
                hv[nt][0] = f2tff(fmaxf(acc[mt][nt][0] + cA.x, 0.f));
                hv[nt][1] = f2tff(fmaxf(acc[mt][nt][1] + cA.y, 0.f));
                hv[nt][2] = f2tff(fmaxf(acc[mt][nt][2] + cB.x, 0.f));
                hv[nt][3] = f2tff(fmaxf(acc[mt][nt][3] + cB.y, 0.f));
            }
            #pragma unroll
            for (int p = 0; p < 2; p++){
                int ds = wn*2 + p;
                sHq[r0*36 + ds*4 + tig] = make_float4(hv[2*p][0], hv[2*p][1], hv[2*p+1][0], hv[2*p+1][1]);
                sHq[r1*36 + ds*4 + tig] = make_float4(hv[2*p][2], hv[2*p][3], hv[2*p+1][2], hv[2*p+1][3]);
            }
        }
        __syncthreads();   // (2) sH ready

        // ===== layer 2: acc = H @ W2 (8 double-k-steps) =====
        #pragma unroll
        for (int mt = 0; mt < 2; mt++)
            #pragma unroll
            for (int nt = 0; nt < 4; nt++)
                #pragma unroll
                for (int q = 0; q < 4; q++) acc[mt][nt][q] = 0.f;

        #pragma unroll
        for (int ds = 0; ds < 8; ds++){
            float4 a0[2], a1[2];
            #pragma unroll
            for (int mt = 0; mt < 2; mt++){
                int r = m0 + mt*16 + gid;
                a0[mt] = sHq[r*36 + ds*4 + tig];
                a1[mt] = sHq[(r+8)*36 + ds*4 + tig];
            }
            #pragma unroll
            for (int nt = 0; nt < 4; nt++){
                float4 w = sW2q[ds*512 + (n0 + nt*8 + gid)*4 + tig];
                #pragma unroll
                for (int mt = 0; mt < 2; mt++){
                    mma8(acc[mt][nt], U(a0[mt].x), U(a1[mt].x), U(a0[mt].y), U(a1[mt].y), U(w.x), U(w.y));
                    mma8(acc[mt][nt], U(a0[mt].z), U(a1[mt].z), U(a0[mt].w), U(a1[mt].w), U(w.z), U(w.w));
                }
            }
        }

        // ===== epilogue 2: segment-max from registers (no smem round trip) =====
        if (sBc[0] == sBc[TM-1]){
            // uniform tile: plain warp max, gid==0 lanes emit
            int g = sBc[0];
            #pragma unroll
            for (int nt = 0; nt < 4; nt++)
                #pragma unroll
                for (int qc = 0; qc < 2; qc++){
                    float v = fmaxf(fmaxf(acc[0][nt][qc], acc[0][nt][2+qc]),
                                    fmaxf(acc[1][nt][qc], acc[1][nt][2+qc]));
                    v = fmaxf(v, __shfl_down_sync(0xffffffffu, v, 4));
                    v = fmaxf(v, __shfl_down_sync(0xffffffffu, v, 8));
                    v = fmaxf(v, __shfl_down_sync(0xffffffffu, v, 16));
                    if (gid == 0){
                        int c = n0 + nt*8 + tig*2 + qc;
                        atomicMaxF(&out[g*DH + c], v + sB2[c]);
                    }
                }
        } else {
            // general: segmented suffix-max over gid (batch monotone within tile)
            #pragma unroll
            for (int R = 0; R < 4; R++){
                const int mt = R >> 1, qr = R & 1;
                int r = m0 + mt*16 + qr*8 + gid;
                int g   = sBc[r];
                int gp  = __shfl_up_sync(0xffffffffu, g, 4);
                int g4  = __shfl_down_sync(0xffffffffu, g, 4);
                int g8  = __shfl_down_sync(0xffffffffu, g, 8);
                int g16 = __shfl_down_sync(0xffffffffu, g, 16);
                bool m4  = (gid < 7) && (g4 == g);
                bool m8  = (gid < 6) && (g8 == g);
                bool m16 = (gid < 4) && (g16 == g);
                bool head = (g >= 0) && (gid == 0 || gp != g);
                #pragma unroll
                for (int nt = 0; nt < 4; nt++)
                    #pragma unroll
                    for (int qc = 0; qc < 2; qc++){
                        float v = acc[mt][nt][qr*2 + qc];
                        float tv;
                        tv = __shfl_down_sync(0xffffffffu, v, 4);  if (m4)  v = fmaxf(v, tv);
                        tv = __shfl_down_sync(0xffffffffu, v, 8);  if (m8)  v = fmaxf(v, tv);
                        tv = __shfl_down_sync(0xffffffffu, v, 16); if (m16) v = fmaxf(v, tv);
                        if (head){
                            int c = n0 + nt*8 + tig*2 + qc;
                            atomicMaxF(&out[g*DH + c], v + sB2[c]);
                        }
                    }
            }
        }

        asm volatile("cp.async.wait_group 0;\n" ::: "memory");
        __syncthreads();   // (3) next sA ready, sH free for next epi1
    }
}

// ---------------------------------------------------------------------------
extern "C" void kernel_launch(void* const* d_in, const int* in_sizes, int n_in,
                              void* d_out, int out_size){
    const float* x     = (const float*)d_in[0];
    const float* pos   = (const float*)d_in[1];
    const int*   batch = (const int*)  d_in[2];
    const float* lf    = (const float*)d_in[3];
    const float* W1    = (const float*)d_in[4];
    const float* b1    = (const float*)d_in[5];
    const float* W2    = (const float*)d_in[6];
    const float* b2    = (const float*)d_in[7];
    float* out = (float*)d_out;
    int n = in_sizes[2];

    cudaFuncSetAttribute(k_main, cudaFuncAttributeMaxDynamicSharedMemorySize, SMEM_BYTES);

    k_init<<<104, 256>>>(W1, W2, out, out_size);
    k_comamin<<<CA_GRID, 256>>>(pos, batch, n);
    k_prep<<<NB, DH>>>(x, pos, batch, lf, W1, b1, out, out_size, n);
    k_main<<<148, 512, SMEM_BYTES>>>(x, pos, batch, b2, out, n);
}

// round 12
// speedup vs baseline: 2.9110x; 1.0082x over previous
#include <cuda_runtime.h>
#include <cstdint>

#define NB 64
#define DIN 64
#define DH 128
#define TM 128

// byte offsets in dynamic smem (16B aligned)
#define OFFB_W1 0            // 5ds*128col*4tig float4 = 40960 B
#define OFFB_A  40960        // 128 rows * 320 B = 40960 B
#define OFFB_H  81920        // 128 rows * 576 B = 73728 B
#define OFFB_B2 155648       // 128 floats
#define OFFB_SB 156160       // 2*128 ints
#define SMEM_BYTES 157184

#define CA_GRID 592

__device__ float g_psum[NB*4];
__device__ unsigned long long g_amin[NB];
__device__ unsigned g_bar;
__device__ __align__(16) float g_cg[NB*DH];
__device__ __align__(16) float4 g_W1p[5*128*4];   // [ds*512 + col*4 + tig]
__device__ __align__(16) float4 g_W2p[8*128*4];

__device__ __forceinline__ unsigned f2tf(float x){
    unsigned u; asm("cvt.rna.tf32.f32 %0, %1;" : "=r"(u) : "f"(x)); return u;
}
__device__ __forceinline__ float f2tff(float x){ return __uint_as_float(f2tf(x)); }
__device__ __forceinline__ uint32_t s2u(const void* p){
    uint32_t a; asm("{ .reg .u64 t; cvta.to.shared.u64 t, %1; cvt.u32.u64 %0, t; }" : "=r"(a) : "l"(p)); return a;
}
__device__ __forceinline__ void atomicMaxF(float* a, float v){
    if (v >= 0.f) atomicMax((int*)a, __float_as_int(v));
    else          atomicMin((unsigned int*)a, __float_as_uint(v));
}
__device__ __forceinline__ void mma8(float (&c)[4], unsigned a0, unsigned a1, unsigned a2, unsigned a3,
                                     unsigned b0, unsigned b1){
    asm volatile("mma.sync.aligned.m16n8k8.row.col.f32.tf32.tf32.f32 "
        "{%0,%1,%2,%3}, {%4,%5,%6,%7}, {%8,%9}, {%0,%1,%2,%3};\n"
        : "+f"(c[0]), "+f"(c[1]), "+f"(c[2]), "+f"(c[3])
        : "r"(a0), "r"(a1), "r"(a2), "r"(a3), "r"(b0), "r"(b1));
}
#define U(x) __float_as_uint(x)

// ---------------------------------------------------------------------------
// launch 0: init + pack weights into 16B-cell layouts
__global__ void k_init(const float* __restrict__ W1, const float* __restrict__ W2,
                       float* out, int out_size){
    int i = blockIdx.x*blockDim.x + threadIdx.x;
    if (i < NB*4) g_psum[i] = 0.f;
    if (i < NB)   g_amin[i] = 0xFFFFFFFFFFFFFFFFULL;
    if (i == 0)   g_bar = 0u;
    if (i < NB*DH && i < out_size) out[i] = __int_as_float(0xff800000);

    if (i < 5*128*4){
        int ds = i >> 9, col = (i >> 2) & 127, tig = i & 3;
        int ch = ds*4 + tig;
        float v[4];
        #pragma unroll
        for (int j = 0; j < 4; j++){
            float w = 0.f;
            if (ch < 16){ int xc = ch*4 + j; w = W1[(DIN + xc)*DH + col]; }
            else if (ch == 16 && j < 3){ w = W1[(2*DIN + j)*DH + col]; }
            v[j] = f2tff(w);
        }
        g_W1p[i] = make_float4(v[0], v[1], v[2], v[3]);
    } else if (i < 5*128*4 + 8*128*4){
        int q = i - 5*128*4;
        int ds = q >> 9, col = (q >> 2) & 127, tig = q & 3;
        float v[4];
        #pragma unroll
        for (int j = 0; j < 4; j++){
            int kh = 32*(ds >> 1) + 16*(ds & 1) + 8*(j >> 1) + tig*2 + (j & 1);
            v[j] = f2tff(W2[kh*DH + col]);
        }
        g_W2p[q] = make_float4(v[0], v[1], v[2], v[3]);
    }
}

// launch 1: fused COM + argmin, device-wide spin barrier (4 CTA/SM guaranteed)
__global__ __launch_bounds__(256, 4) void k_comamin(
    const float* __restrict__ pos, const int* __restrict__ batch, int n){
    const int stride = CA_GRID*256;
    const int base = blockIdx.x*256 + threadIdx.x;
    const int trips = (n + stride - 1) / stride;

    for (int j = 0; j < trips; j++){
        int i = base + j*stride;
        int b = -1; float px=0.f, py=0.f, pz=0.f, pc=0.f;
        if (i < n){ b = batch[i]; px = pos[3*i]; py = pos[3*i+1]; pz = pos[3*i+2]; pc = 1.f; }
        int b0 = __shfl_sync(0xffffffffu, b, 0);
        bool uni = __all_sync(0xffffffffu, b == b0);
        if (uni){
            #pragma unroll
            for (int o = 16; o; o >>= 1){
                px += __shfl_down_sync(0xffffffffu, px, o);
                py += __shfl_down_sync(0xffffffffu, py, o);
                pz += __shfl_down_sync(0xffffffffu, pz, o);
                pc += __shfl_down_sync(0xffffffffu, pc, o);
            }
            if ((threadIdx.x & 31) == 0 && b0 >= 0){
                atomicAdd(&g_psum[b0*4+0], px); atomicAdd(&g_psum[b0*4+1], py);
                atomicAdd(&g_psum[b0*4+2], pz); atomicAdd(&g_psum[b0*4+3], pc);
            }
        } else if (b >= 0){
            atomicAdd(&g_psum[b*4+0], px); atomicAdd(&g_psum[b*4+1], py);
            atomicAdd(&g_psum[b*4+2], pz); atomicAdd(&g_psum[b*4+3], pc);
        }
    }

    __threadfence();
    __syncthreads();
    if (threadIdx.x == 0){
        atomicAdd(&g_bar, 1u);
        while (atomicAdd(&g_bar, 0u) < (unsigned)CA_GRID) __nanosleep(64);
    }
    __syncthreads();
    __threadfence();

    for (int j = 0; j < trips; j++){
        int i = base + j*stride;
        int b = -1; unsigned long long key = 0xFFFFFFFFFFFFFFFFULL;
        if (i < n){
            b = batch[i];
            float cnt = fmaxf(g_psum[b*4+3], 1.f);
            float inv = 1.f / cnt;
            float dx = pos[3*i]   - g_psum[b*4+0]*inv;
            float dy = pos[3*i+1] - g_psum[b*4+1]*inv;
            float dz = pos[3*i+2] - g_psum[b*4+2]*inv;
            float d2 = dx*dx + dy*dy + dz*dz;
            key = ((unsigned long long)__float_as_uint(d2) << 32) | (unsigned)i;
        }
        int b0 = __shfl_sync(0xffffffffu, b, 0);
        bool uni = __all_sync(0xffffffffu, b == b0);
        if (uni){
            #pragma unroll
            for (int o = 16; o; o >>= 1){
                unsigned long long k2 = __shfl_down_sync(0xffffffffu, key, o);
                if (k2 < key) key = k2;
            }
            if ((threadIdx.x & 31) == 0 && b0 >= 0) atomicMin(&g_amin[b0], key);
        } else if (b >= 0){
            atomicMin(&g_amin[b], key);
        }
    }
}

// launch 2: per-graph bias cg + aux outputs
__global__ void k_prep(const float* __restrict__ x, const float* __restrict__ pos,
                       const int* __restrict__ batch, const float* __restrict__ lf,
                       const float* __restrict__ W1, const float* __restrict__ b1,
                       float* out, int out_size, int n){
    int g = blockIdx.x, c = threadIdx.x;
    __shared__ float sxd[DIN];
    __shared__ float sp3[3];
    __shared__ int sidx;
    if (c == 0){
        int id = (int)(unsigned)(g_amin[g] & 0xFFFFFFFFULL);
        if (id > n-1) id = n-1;
        sidx = id;
    }
    __syncthreads();
    int idx = sidx;
    if (c < DIN) sxd[c] = x[(size_t)idx*DIN + c];
    if (c < 3)   sp3[c] = pos[idx*3 + c];
    __syncthreads();
    float acc = b1[c];
    #pragma unroll 8
    for (int k = 0; k < DIN; k++)
        acc += sxd[k] * (W1[k*DH + c] - W1[(DIN+k)*DH + c]);
    #pragma unroll
    for (int j = 0; j < 3; j++)
        acc -= sp3[j] * W1[(2*DIN+j)*DH + c];
    g_cg[g*DH + c] = acc;

    if (out_size >= NB*DH + NB*3 + NB + NB*9){
        if (c < 3)  out[NB*DH + g*3 + c] = pos[idx*3 + c];
        if (c == 3) out[NB*DH + NB*3 + g] = (float)batch[idx];
        if (c < 9)  out[NB*DH + NB*3 + NB + g*9 + c] = lf[(size_t)idx*9 + c];
    }
}

// ---------------------------------------------------------------------------
__device__ __forceinline__ void issue_load(char* smem, uint32_t sA_u,
        const float* __restrict__ x, const float* __restrict__ pos,
        const int* __restrict__ batch, int n, int base, int slot, int tid)
{
    #pragma unroll
    for (int rep = 0; rep < 8; rep++){
        int i = tid + rep*256;
        int r = i >> 4, ch = i & 15;
        int row = base + r;
        uint32_t dst = sA_u + (uint32_t)(r*320 + ch*16);
        const float* src = x + (size_t)(row < n ? row : 0)*DIN + ch*4;
        unsigned pb = (row < n) ? 16u : 0u;
        asm volatile("cp.async.cg.shared.global [%0], [%1], 16, %2;\n"
                     :: "r"(dst), "l"(src), "r"(pb) : "memory");
    }
    asm volatile("cp.async.commit_group;\n" ::: "memory");
    if (tid < TM){
        int row = base + tid;
        float4 p = make_float4(0.f, 0.f, 0.f, 0.f);
        int g = -1;
        if (row < n){ p.x = pos[3*row]; p.y = pos[3*row+1]; p.z = pos[3*row+2]; g = batch[row]; }
        *(float4*)(smem + OFFB_A + tid*320 + 256) = p;
        ((int*)(smem + OFFB_SB))[slot*128 + tid] = g;
    }
}

__global__ __launch_bounds__(256, 1)
void k_main(const float* __restrict__ x, const float* __restrict__ pos,
            const int* __restrict__ batch, const float* __restrict__ b2,
            float* __restrict__ out, int n)
{
    extern __shared__ __align__(16) char smem[];
    const float4* sW1q = (const float4*)(smem + OFFB_W1);
    const float4* sAq  = (const float4*)(smem + OFFB_A);
    float4*       sHq  = (float4*)(smem + OFFB_H);
    float*        sB2  = (float*)(smem + OFFB_B2);

    const int tid = threadIdx.x, lane = tid & 31, warp = tid >> 5;
    const int gid = lane >> 2, tig = lane & 3;
    const int wm = warp >> 2, wn = warp & 3;   // 2 row bands x 4 col bands
    const int m0 = wm*64, n0 = wn*32;
    const int numTiles = (n + TM - 1) / TM;
    const uint32_t sA_u = s2u(smem + OFFB_A);

    // prologue: W1 to smem, b2, zero A pad cells, W2 slice -> registers
    {
        float4* w1 = (float4*)(smem + OFFB_W1);
        for (int i = tid; i < 5*128*4; i += 256) w1[i] = g_W1p[i];
        if (tid < DH) sB2[tid] = b2[tid];
        if (tid < TM){
            float4* z = (float4*)(smem + OFFB_A + tid*320 + 272);
            z[0] = z[1] = z[2] = make_float4(0.f,0.f,0.f,0.f);
        }
    }
    float4 wreg[8][4];
    #pragma unroll
    for (int ds = 0; ds < 8; ds++)
        #pragma unroll
        for (int nt = 0; nt < 4; nt++)
            wreg[ds][nt] = g_W2p[ds*512 + (n0 + nt*8 + gid)*4 + tig];

    const int t0 = blockIdx.x;
    if (t0 < numTiles) issue_load(smem, sA_u, x, pos, batch, n, t0*TM, 0, tid);
    asm volatile("cp.async.wait_group 0;\n" ::: "memory");
    __syncthreads();

    float acc[4][4][4];
    int it = 0;
    for (int t = t0; t < numTiles; t += 148, it++){
        const int par = it & 1;
        const int tn = t + 148;
        const int* sBc = (const int*)(smem + OFFB_SB) + par*128;

        // ===== layer 1: acc = A @ W1 (5 double-k-steps) =====
        #pragma unroll
        for (int mt = 0; mt < 4; mt++)
            #pragma unroll
            for (int nt = 0; nt < 4; nt++)
                #pragma unroll
                for (int q = 0; q < 4; q++) acc[mt][nt][q] = 0.f;

        #pragma unroll
        for (int ds = 0; ds < 5; ds++){
            float4 w1f[4];
            #pragma unroll
            for (int nt = 0; nt < 4; nt++)
                w1f[nt] = sW1q[ds*512 + (n0 + nt*8 + gid)*4 + tig];
            #pragma unroll
            for (int mt = 0; mt < 4; mt++){
                int r = m0 + mt*16 + gid;
                float4 a0 = sAq[r*20 + ds*4 + tig];
                float4 a1 = sAq[(r+8)*20 + ds*4 + tig];
                #pragma unroll
                for (int nt = 0; nt < 4; nt++){
                    mma8(acc[mt][nt], U(a0.x), U(a1.x), U(a0.y), U(a1.y), U(w1f[nt].x), U(w1f[nt].y));
                    mma8(acc[mt][nt], U(a0.z), U(a1.z), U(a0.w), U(a1.w), U(w1f[nt].z), U(w1f[nt].w));
                }
            }
        }
        __syncthreads();   // (1) sA reads done

        // prefetch next tile into sA
        if (tn < numTiles) issue_load(smem, sA_u, x, pos, batch, n, tn*TM, 1 - par, tid);

        // ===== epilogue 1: h = relu(acc + cg[g]) -> sH packs (STS.128) =====
        #pragma unroll
        for (int mt = 0; mt < 4; mt++){
            int r0 = m0 + mt*16 + gid, r1 = r0 + 8;
            int g0 = sBc[r0], g1 = sBc[r1];
            const float2* cg0 = (const float2*)(g_cg + (size_t)(g0 < 0 ? 0 : g0)*DH);
            const float2* cg1 = (const float2*)(g_cg + (size_t)(g1 < 0 ? 0 : g1)*DH);
            float hv[4][4];
            #pragma unroll
            for (int nt = 0; nt < 4; nt++){
                int c0 = n0 + nt*8 + tig*2;
                float2 cA = __ldg(&cg0[c0 >> 1]);
                float2 cB = __ldg(&cg1[c0 >> 1]);
                hv[nt][0] = f2tff(fmaxf(acc[mt][nt][0] + cA.x, 0.f));
                hv[nt][1] = f2tff(fmaxf(acc[mt][nt][1] + cA.y, 0.f));
                hv[nt][2] = f2tff(fmaxf(acc[mt][nt][2] + cB.x, 0.f));
                hv[nt][3] = f2tff(fmaxf(acc[mt][nt][3] + cB.y, 0.f));
            }
            #pragma unroll
            for (int p = 0; p < 2; p++){
                int ds = wn*2 + p;
                sHq[r0*36 + ds*4 + tig] = make_float4(hv[2*p][0], hv[2*p][1], hv[2*p+1][0], hv[2*p+1][1]);
                sHq[r1*36 + ds*4 + tig] = make_float4(hv[2*p][2], hv[2*p][3], hv[2*p+1][2], hv[2*p+1][3]);
            }
        }
        __syncthreads();   // (2) sH ready

        // ===== layer 2: acc = H @ W2reg (8 double-k-steps) =====
        #pragma unroll
        for (int mt = 0; mt < 4; mt++)
            #pragma unroll
            for (int nt = 0; nt < 4; nt++)
                #pragma unroll
                for (int q = 0; q < 4; q++) acc[mt][nt][q] = 0.f;

        #pragma unroll
        for (int ds = 0; ds < 8; ds++){
            #pragma unroll
            for (int mt = 0; mt < 4; mt++){
                int r = m0 + mt*16 + gid;
                float4 a0 = sHq[r*36 + ds*4 + tig];
                float4 a1 = sHq[(r+8)*36 + ds*4 + tig];
                #pragma unroll
                for (int nt = 0; nt < 4; nt++){
                    mma8(acc[mt][nt], U(a0.x), U(a1.x), U(a0.y), U(a1.y), U(wreg[ds][nt].x), U(wreg[ds][nt].y));
                    mma8(acc[mt][nt], U(a0.z), U(a1.z), U(a0.w), U(a1.w), U(wreg[ds][nt].z), U(wreg[ds][nt].w));
                }
            }
        }

        // ===== epilogue 2: segment-max from registers =====
        if (sBc[0] == sBc[TM-1]){
            int g = sBc[0];
            #pragma unroll
            for (int nt = 0; nt < 4; nt++)
                #pragma unroll
                for (int qc = 0; qc < 2; qc++){
                    float v = __int_as_float(0xff800000);
                    #pragma unroll
                    for (int mt = 0; mt < 4; mt++)
                        v = fmaxf(v, fmaxf(acc[mt][nt][qc], acc[mt][nt][2+qc]));
                    v = fmaxf(v, __shfl_down_sync(0xffffffffu, v, 4));
                    v = fmaxf(v, __shfl_down_sync(0xffffffffu, v, 8));
                    v = fmaxf(v, __shfl_down_sync(0xffffffffu, v, 16));
                    if (gid == 0){
                        int c = n0 + nt*8 + tig*2 + qc;
                        atomicMaxF(&out[g*DH + c], v + sB2[c]);
                    }
                }
        } else {
            #pragma unroll
            for (int R = 0; R < 8; R++){
                const int mt = R >> 1, qr = R & 1;
                int r = m0 + mt*16 + qr*8 + gid;
                int g   = sBc[r];
                int gp  = __shfl_up_sync(0xffffffffu, g, 4);
                int g4  = __shfl_down_sync(0xffffffffu, g, 4);
                int g8  = __shfl_down_sync(0xffffffffu, g, 8);
                int g16 = __shfl_down_sync(0xffffffffu, g, 16);
                bool m4  = (gid < 7) && (g4 == g);
                bool m8  = (gid < 6) && (g8 == g);
                bool m16 = (gid < 4) && (g16 == g);
                bool head = (g >= 0) && (gid == 0 || gp != g);
                #pragma unroll
                for (int nt = 0; nt < 4; nt++)
                    #pragma unroll
                    for (int qc = 0; qc < 2; qc++){
                        float v = acc[mt][nt][qr*2 + qc];
                        float tv;
                        tv = __shfl_down_sync(0xffffffffu, v, 4);  if (m4)  v = fmaxf(v, tv);
                        tv = __shfl_down_sync(0xffffffffu, v, 8);  if (m8)  v = fmaxf(v, tv);
                        tv = __shfl_down_sync(0xffffffffu, v, 16); if (m16) v = fmaxf(v, tv);
                        if (head){
                            int c = n0 + nt*8 + tig*2 + qc;
                            atomicMaxF(&out[g*DH + c], v + sB2[c]);
                        }
                    }
            }
        }

        asm volatile("cp.async.wait_group 0;\n" ::: "memory");
        __syncthreads();   // (3) next sA ready, sH free
    }
}

// ---------------------------------------------------------------------------
extern "C" void kernel_launch(void* const* d_in, const int* in_sizes, int n_in,
                              void* d_out, int out_size){
    const float* x     = (const float*)d_in[0];
    const float* pos   = (const float*)d_in[1];
    const int*   batch = (const int*)  d_in[2];
    const float* lf    = (const float*)d_in[3];
    const float* W1    = (const float*)d_in[4];
    const float* b1    = (const float*)d_in[5];
    const float* W2    = (const float*)d_in[6];
    const float* b2    = (const float*)d_in[7];
    float* out = (float*)d_out;
    int n = in_sizes[2];

    cudaFuncSetAttribute(k_main, cudaFuncAttributeMaxDynamicSharedMemorySize, SMEM_BYTES);

    k_init<<<104, 256>>>(W1, W2, out, out_size);
    k_comamin<<<CA_GRID, 256>>>(pos, batch, n);
    k_prep<<<NB, DH>>>(x, pos, batch, lf, W1, b1, out, out_size, n);
    k_main<<<148, 256, SMEM_BYTES>>>(x, pos, batch, b2, out, n);
}

// round 15
// speedup vs baseline: 3.1526x; 1.0830x over previous
#include <cuda_runtime.h>
#include <cstdint>

#define NB 64
#define DIN 64
#define DH 128
#define TM 128

// byte offsets in dynamic smem (16B aligned)
#define OFFB_W1 0            // 5ds*128col*4tig float4 = 40960 B
#define OFFB_W2 40960        // W2 ds4..7: 4*512 float4 = 32768 B
#define OFFB_A  73728        // 128 rows * 320 B = 40960 B
#define OFFB_H  114688       // 128 rows * 576 B = 73728 B
#define OFFB_B2 188416       // 128 floats
#define OFFB_SB 188928       // 2*128 ints
#define SMEM_BYTES 189952

#define CA_GRID 592

__device__ float g_psum[NB*4];
__device__ unsigned long long g_amin[NB];
__device__ unsigned g_bar;
__device__ __align__(16) float g_cg[NB*DH];
__device__ __align__(16) float g_Wd[DIN*DH];      // W1a - W1b (fp32)
__device__ __align__(16) float4 g_W1p[5*128*4];   // [ds*512 + col*4 + tig]
__device__ __align__(16) float4 g_W2p[8*128*4];

__device__ __forceinline__ unsigned f2tf(float x){
    unsigned u; asm("cvt.rna.tf32.f32 %0, %1;" : "=r"(u) : "f"(x)); return u;
}
__device__ __forceinline__ float f2tff(float x){ return __uint_as_float(f2tf(x)); }
__device__ __forceinline__ uint32_t s2u(const void* p){
    uint32_t a; asm("{ .reg .u64 t; cvta.to.shared.u64 t, %1; cvt.u32.u64 %0, t; }" : "=r"(a) : "l"(p)); return a;
}
__device__ __forceinline__ void atomicMaxF(float* a, float v){
    if (v >= 0.f) atomicMax((int*)a, __float_as_int(v));
    else          atomicMin((unsigned int*)a, __float_as_uint(v));
}
__device__ __forceinline__ void mma8(float (&c)[4], unsigned a0, unsigned a1, unsigned a2, unsigned a3,
                                     unsigned b0, unsigned b1){
    asm volatile("mma.sync.aligned.m16n8k8.row.col.f32.tf32.tf32.f32 "
        "{%0,%1,%2,%3}, {%4,%5,%6,%7}, {%8,%9}, {%0,%1,%2,%3};\n"
        : "+f"(c[0]), "+f"(c[1]), "+f"(c[2]), "+f"(c[3])
        : "r"(a0), "r"(a1), "r"(a2), "r"(a3), "r"(b0), "r"(b1));
}
#define U(x) __float_as_uint(x)

// ---------------------------------------------------------------------------
// launch 0: init + pack weights + Wd
__global__ void k_init(const float* __restrict__ W1, const float* __restrict__ W2,
                       float* out, int out_size){
    int i = blockIdx.x*blockDim.x + threadIdx.x;
    if (i < NB*4) g_psum[i] = 0.f;
    if (i < NB)   g_amin[i] = 0xFFFFFFFFFFFFFFFFULL;
    if (i == 0)   g_bar = 0u;
    if (i < NB*DH && i < out_size) out[i] = __int_as_float(0xff800000);
    if (i < DIN*DH){
        int k = i >> 7, c = i & 127;
        g_Wd[i] = W1[k*DH + c] - W1[(DIN+k)*DH + c];
    }
    if (i < 5*128*4){
        int ds = i >> 9, col = (i >> 2) & 127, tig = i & 3;
        int ch = ds*4 + tig;
        float v[4];
        #pragma unroll
        for (int j = 0; j < 4; j++){
            float w = 0.f;
            if (ch < 16){ int xc = ch*4 + j; w = W1[(DIN + xc)*DH + col]; }
            else if (ch == 16 && j < 3){ w = W1[(2*DIN + j)*DH + col]; }
            v[j] = f2tff(w);
        }
        g_W1p[i] = make_float4(v[0], v[1], v[2], v[3]);
    } else if (i < 5*128*4 + 8*128*4){
        int q = i - 5*128*4;
        int ds = q >> 9, col = (q >> 2) & 127, tig = q & 3;
        float v[4];
        #pragma unroll
        for (int j = 0; j < 4; j++){
            int kh = 32*(ds >> 1) + 16*(ds & 1) + 8*(j >> 1) + tig*2 + (j & 1);
            v[j] = f2tff(W2[kh*DH + col]);
        }
        g_W2p[q] = make_float4(v[0], v[1], v[2], v[3]);
    }
}

// launch 1: COM + argmin + per-graph prep, 2 device-wide spin barriers
__global__ __launch_bounds__(256, 4) void k_comamin(
    const float* __restrict__ pos, const int* __restrict__ batch,
    const float* __restrict__ x, const float* __restrict__ lf,
    const float* __restrict__ W1, const float* __restrict__ b1,
    float* out, int out_size, int n){
    const int stride = CA_GRID*256;
    const int base = blockIdx.x*256 + threadIdx.x;
    const int trips = (n + stride - 1) / stride;

    // phase 1: COM partial sums
    for (int j = 0; j < trips; j++){
        int i = base + j*stride;
        int b = -1; float px=0.f, py=0.f, pz=0.f, pc=0.f;
        if (i < n){ b = batch[i]; px = pos[3*i]; py = pos[3*i+1]; pz = pos[3*i+2]; pc = 1.f; }
        int b0 = __shfl_sync(0xffffffffu, b, 0);
        bool uni = __all_sync(0xffffffffu, b == b0);
        if (uni){
            #pragma unroll
            for (int o = 16; o; o >>= 1){
                px += __shfl_down_sync(0xffffffffu, px, o);
                py += __shfl_down_sync(0xffffffffu, py, o);
                pz += __shfl_down_sync(0xffffffffu, pz, o);
                pc += __shfl_down_sync(0xffffffffu, pc, o);
            }
            if ((threadIdx.x & 31) == 0 && b0 >= 0){
                atomicAdd(&g_psum[b0*4+0], px); atomicAdd(&g_psum[b0*4+1], py);
                atomicAdd(&g_psum[b0*4+2], pz); atomicAdd(&g_psum[b0*4+3], pc);
            }
        } else if (b >= 0){
            atomicAdd(&g_psum[b*4+0], px); atomicAdd(&g_psum[b*4+1], py);
            atomicAdd(&g_psum[b*4+2], pz); atomicAdd(&g_psum[b*4+3], pc);
        }
    }

    __threadfence();
    __syncthreads();
    if (threadIdx.x == 0){
        atomicAdd(&g_bar, 1u);
        while (atomicAdd(&g_bar, 0u) < (unsigned)CA_GRID) __nanosleep(64);
    }
    __syncthreads();
    __threadfence();

    // phase 2: argmin dist-to-COM
    for (int j = 0; j < trips; j++){
        int i = base + j*stride;
        int b = -1; unsigned long long key = 0xFFFFFFFFFFFFFFFFULL;
        if (i < n){
            b = batch[i];
            float cnt = fmaxf(g_psum[b*4+3], 1.f);
            float inv = 1.f / cnt;
            float dx = pos[3*i]   - g_psum[b*4+0]*inv;
            float dy = pos[3*i+1] - g_psum[b*4+1]*inv;
            float dz = pos[3*i+2] - g_psum[b*4+2]*inv;
            float d2 = dx*dx + dy*dy + dz*dz;
            key = ((unsigned long long)__float_as_uint(d2) << 32) | (unsigned)i;
        }
        int b0 = __shfl_sync(0xffffffffu, b, 0);
        bool uni = __all_sync(0xffffffffu, b == b0);
        if (uni){
            #pragma unroll
            for (int o = 16; o; o >>= 1){
                unsigned long long k2 = __shfl_down_sync(0xffffffffu, key, o);
                if (k2 < key) key = k2;
            }
            if ((threadIdx.x & 31) == 0 && b0 >= 0) atomicMin(&g_amin[b0], key);
        } else if (b >= 0){
            atomicMin(&g_amin[b], key);
        }
    }

    __threadfence();
    __syncthreads();
    if (threadIdx.x == 0){
        atomicAdd(&g_bar, 1u);
        while (atomicAdd(&g_bar, 0u) < 2u*(unsigned)CA_GRID) __nanosleep(64);
    }
    __syncthreads();
    __threadfence();

    // phase 3: per-graph bias cg + aux outputs (blocks 0..31, 2 graphs each)
    if (blockIdx.x < NB/2){
        const int half = threadIdx.x >> 7;          // 0..1
        const int c = threadIdx.x & 127;
        const int g = blockIdx.x*2 + half;
        __shared__ float sxd[2][DIN];
        __shared__ float sp3[2][3];
        __shared__ int sidx[2];
        if (c == 0){
            int id = (int)(unsigned)(g_amin[g] & 0xFFFFFFFFULL);
            if (id > n-1) id = n-1;
            sidx[half] = id;
        }
        __syncthreads();
        int idx = sidx[half];
        if (c < DIN) sxd[half][c] = x[(size_t)idx*DIN + c];
        if (c < 3)   sp3[half][c] = pos[idx*3 + c];
        __syncthreads();
        float acc = b1[c];
        #pragma unroll 8
        for (int k = 0; k < DIN; k++)
            acc += sxd[half][k] * g_Wd[k*DH + c];
        #pragma unroll
        for (int j = 0; j < 3; j++)
            acc -= sp3[half][j] * W1[(2*DIN+j)*DH + c];
        g_cg[g*DH + c] = acc;

        if (out_size >= NB*DH + NB*3 + NB + NB*9){
            if (c < 3)  out[NB*DH + g*3 + c] = pos[idx*3 + c];
            if (c == 3) out[NB*DH + NB*3 + g] = (float)batch[idx];
            if (c < 9)  out[NB*DH + NB*3 + NB + g*9 + c] = lf[(size_t)idx*9 + c];
        }
    }
}

// ---------------------------------------------------------------------------
__device__ __forceinline__ void issue_load(char* smem, uint32_t sA_u,
        const float* __restrict__ x, const float* __restrict__ pos,
        const int* __restrict__ batch, int n, int base, int slot, int tid)
{
    #pragma unroll
    for (int rep = 0; rep < 4; rep++){
        int i = tid + rep*512;
        int r = i >> 4, ch = i & 15;
        int row = base + r;
        uint32_t dst = sA_u + (uint32_t)(r*320 + ch*16);
        const float* src = x + (size_t)(row < n ? row : 0)*DIN + ch*4;
        unsigned pb = (row < n) ? 16u : 0u;
        asm volatile("cp.async.cg.shared.global [%0], [%1], 16, %2;\n"
                     :: "r"(dst), "l"(src), "r"(pb) : "memory");
    }
    asm volatile("cp.async.commit_group;\n" ::: "memory");
    if (tid < TM){
        int row = base + tid;
        float4 p = make_float4(0.f, 0.f, 0.f, 0.f);
        int g = -1;
        if (row < n){ p.x = pos[3*row]; p.y = pos[3*row+1]; p.z = pos[3*row+2]; g = batch[row]; }
        *(float4*)(smem + OFFB_A + tid*320 + 256) = p;
        ((int*)(smem + OFFB_SB))[slot*128 + tid] = g;
    }
}

// launch 2: main fused kernel, 512 threads, warp tile 64x16 (2x8 warp grid)
__global__ __launch_bounds__(512, 1)
void k_main(const float* __restrict__ x, const float* __restrict__ pos,
            const int* __restrict__ batch, const float* __restrict__ b2,
            float* __restrict__ out, int n)
{
    extern __shared__ __align__(16) char smem[];
    const float4* sW1q = (const float4*)(smem + OFFB_W1);
    const float4* sW2q = (const float4*)(smem + OFFB_W2);   // ds 4..7 only
    const float4* sAq  = (const float4*)(smem + OFFB_A);
    float4*       sHq  = (float4*)(smem + OFFB_H);
    float*        sB2  = (float*)(smem + OFFB_B2);

    const int tid = threadIdx.x, lane = tid & 31, warp = tid >> 5;
    const int gid = lane >> 2, tig = lane & 3;
    const int wm = warp & 1, wn = warp >> 1;   // 2 row bands (64) x 8 col bands (16)
    const int m0 = wm*64, n0 = wn*16;
    const int numTiles = (n + TM - 1) / TM;
    const uint32_t sA_u = s2u(smem + OFFB_A);

    // prologue: W1 + W2(ds4..7) to smem, b2, zero A pad, W2(ds0..3) -> regs
    {
        float4* w1 = (float4*)(smem + OFFB_W1);
        float4* w2 = (float4*)(smem + OFFB_W2);
        for (int i = tid; i < 5*128*4; i += 512) w1[i] = g_W1p[i];
        for (int i = tid; i < 4*128*4; i += 512) w2[i] = g_W2p[i + 2048];
        if (tid < DH) sB2[tid] = b2[tid];
        if (tid < TM){
            float4* z = (float4*)(smem + OFFB_A + tid*320 + 272);
            z[0] = z[1] = z[2] = make_float4(0.f,0.f,0.f,0.f);
        }
    }
    float4 wreg[4][2];
    #pragma unroll
    for (int ds = 0; ds < 4; ds++)
        #pragma unroll
        for (int nt = 0; nt < 2; nt++)
            wreg[ds][nt] = g_W2p[ds*512 + (n0 + nt*8 + gid)*4 + tig];

    const int t0 = blockIdx.x;
    if (t0 < numTiles) issue_load(smem, sA_u, x, pos, batch, n, t0*TM, 0, tid);
    asm volatile("cp.async.wait_group 0;\n" ::: "memory");
    __syncthreads();

    float acc[4][2][4];
    int it = 0;
    for (int t = t0; t < numTiles; t += 148, it++){
        const int par = it & 1;
        const int tn = t + 148;
        const int* sBc = (const int*)(smem + OFFB_SB) + par*128;

        // ===== layer 1: acc = A @ W1 (5 double-k-steps) =====
        #pragma unroll
        for (int mt = 0; mt < 4; mt++)
            #pragma unroll
            for (int nt = 0; nt < 2; nt++)
                #pragma unroll
                for (int q = 0; q < 4; q++) acc[mt][nt][q] = 0.f;

        #pragma unroll
        for (int ds = 0; ds < 5; ds++){
            float4 w1f[2];
            #pragma unroll
            for (int nt = 0; nt < 2; nt++)
                w1f[nt] = sW1q[ds*512 + (n0 + nt*8 + gid)*4 + tig];
            #pragma unroll
            for (int mt = 0; mt < 4; mt++){
                int r = m0 + mt*16 + gid;
                float4 a0 = sAq[r*20 + ds*4 + tig];
                float4 a1 = sAq[(r+8)*20 + ds*4 + tig];
                #pragma unroll
                for (int nt = 0; nt < 2; nt++){
                    mma8(acc[mt][nt], U(a0.x), U(a1.x), U(a0.y), U(a1.y), U(w1f[nt].x), U(w1f[nt].y));
                    mma8(acc[mt][nt], U(a0.z), U(a1.z), U(a0.w), U(a1.w), U(w1f[nt].z), U(w1f[nt].w));
                }
            }
        }
        __syncthreads();   // (1) sA reads done

        if (tn < numTiles) issue_load(smem, sA_u, x, pos, batch, n, tn*TM, 1 - par, tid);

        // ===== epilogue 1: h = relu(acc + cg[g]) -> sH cell ds=wn =====
        #pragma unroll
        for (int mt = 0; mt < 4; mt++){
            int r0 = m0 + mt*16 + gid, r1 = r0 + 8;
            int g0 = sBc[r0], g1 = sBc[r1];
            const float2* cg0 = (const float2*)(g_cg + (size_t)(g0 < 0 ? 0 : g0)*DH);
            const float2* cg1 = (const float2*)(g_cg + (size_t)(g1 < 0 ? 0 : g1)*DH);
            float hv[2][4];
            #pragma unroll
            for (int nt = 0; nt < 2; nt++){
                int c0 = n0 + nt*8 + tig*2;
                float2 cA = __ldg(&cg0[c0 >> 1]);
                float2 cB = __ldg(&cg1[c0 >> 1]);
                hv[nt][0] = f2tff(fmaxf(acc[mt][nt][0] + cA.x, 0.f));
                hv[nt][1] = f2tff(fmaxf(acc[mt][nt][1] + cA.y, 0.f));
                hv[nt][2] = f2tff(fmaxf(acc[mt][nt][2] + cB.x, 0.f));
                hv[nt][3] = f2tff(fmaxf(acc[mt][nt][3] + cB.y, 0.f));
            }
            sHq[r0*36 + wn*4 + tig] = make_float4(hv[0][0], hv[0][1], hv[1][0], hv[1][1]);
            sHq[r1*36 + wn*4 + tig] = make_float4(hv[0][2], hv[0][3], hv[1][2], hv[1][3]);
        }
        __syncthreads();   // (2) sH ready

        // ===== layer 2: acc = H @ W2 (regs ds0-3, smem ds4-7) =====
        #pragma unroll
        for (int mt = 0; mt < 4; mt++)
            #pragma unroll
            for (int nt = 0; nt < 2; nt++)
                #pragma unroll
                for (int q = 0; q < 4; q++) acc[mt][nt][q] = 0.f;

        #pragma unroll
        for (int ds = 0; ds < 8; ds++){
            float4 w2f[2];
            #pragma unroll
            for (int nt = 0; nt < 2; nt++){
                if (ds < 4) w2f[nt] = wreg[ds][nt];
                else        w2f[nt] = sW2q[(ds-4)*512 + (n0 + nt*8 + gid)*4 + tig];
            }
            #pragma unroll
            for (int mt = 0; mt < 4; mt++){
                int r = m0 + mt*16 + gid;
                float4 a0 = sHq[r*36 + ds*4 + tig];
                float4 a1 = sHq[(r+8)*36 + ds*4 + tig];
                #pragma unroll
                for (int nt = 0; nt < 2; nt++){
                    mma8(acc[mt][nt], U(a0.x), U(a1.x), U(a0.y), U(a1.y), U(w2f[nt].x), U(w2f[nt].y));
                    mma8(acc[mt][nt], U(a0.z), U(a1.z), U(a0.w), U(a1.w), U(w2f[nt].z), U(w2f[nt].w));
                }
            }
        }

        // ===== epilogue 2: segment-max from registers =====
        if (sBc[0] == sBc[TM-1]){
            int g = sBc[0];
            #pragma unroll
            for (int nt = 0; nt < 2; nt++)
                #pragma unroll
                for (int qc = 0; qc < 2; qc++){
                    float v = __int_as_float(0xff800000);
                    #pragma unroll
                    for (int mt = 0; mt < 4; mt++)
                        v = fmaxf(v, fmaxf(acc[mt][nt][qc], acc[mt][nt][2+qc]));
                    v = fmaxf(v, __shfl_down_sync(0xffffffffu, v, 4));
                    v = fmaxf(v, __shfl_down_sync(0xffffffffu, v, 8));
                    v = fmaxf(v, __shfl_down_sync(0xffffffffu, v, 16));
                    if (gid == 0){
                        int c = n0 + nt*8 + tig*2 + qc;
                        atomicMaxF(&out[g*DH + c], v + sB2[c]);
                    }
                }
        } else {
            #pragma unroll
            for (int R = 0; R < 8; R++){
                const int mt = R >> 1, qr = R & 1;
                int r = m0 + mt*16 + qr*8 + gid;
                int g   = sBc[r];
                int gp  = __shfl_up_sync(0xffffffffu, g, 4);
                int g4  = __shfl_down_sync(0xffffffffu, g, 4);
                int g8  = __shfl_down_sync(0xffffffffu, g, 8);
                int g16 = __shfl_down_sync(0xffffffffu, g, 16);
                bool m4  = (gid < 7) && (g4 == g);
                bool m8  = (gid < 6) && (g8 == g);
                bool m16 = (gid < 4) && (g16 == g);
                bool head = (g >= 0) && (gid == 0 || gp != g);
                #pragma unroll
                for (int nt = 0; nt < 2; nt++)
                    #pragma unroll
                    for (int qc = 0; qc < 2; qc++){
                        float v = acc[mt][nt][qr*2 + qc];
                        float tv;
                        tv = __shfl_down_sync(0xffffffffu, v, 4);  if (m4)  v = fmaxf(v, tv);
                        tv = __shfl_down_sync(0xffffffffu, v, 8);  if (m8)  v = fmaxf(v, tv);
                        tv = __shfl_down_sync(0xffffffffu, v, 16); if (m16) v = fmaxf(v, tv);
                        if (head){
                            int c = n0 + nt*8 + tig*2 + qc;
                            atomicMaxF(&out[g*DH + c], v + sB2[c]);
                        }
                    }
            }
        }

        asm volatile("cp.async.wait_group 0;\n" ::: "memory");
        __syncthreads();   // (3) next sA ready, sH free
    }
}

// ---------------------------------------------------------------------------
extern "C" void kernel_launch(void* const* d_in, const int* in_sizes, int n_in,
                              void* d_out, int out_size){
    const float* x     = (const float*)d_in[0];
    const float* pos   = (const float*)d_in[1];
    const int*   batch = (const int*)  d_in[2];
    const float* lf    = (const float*)d_in[3];
    const float* W1    = (const float*)d_in[4];
    const float* b1    = (const float*)d_in[5];
    const float* W2    = (const float*)d_in[6];
    const float* b2    = (const float*)d_in[7];
    float* out = (float*)d_out;
    int n = in_sizes[2];

    cudaFuncSetAttribute(k_main, cudaFuncAttributeMaxDynamicSharedMemorySize, SMEM_BYTES);

    k_init<<<104, 256>>>(W1, W2, out, out_size);
    k_comamin<<<CA_GRID, 256>>>(pos, batch, x, lf, W1, b1, out, out_size, n);
    k_main<<<148, 512, SMEM_BYTES>>>(x, pos, batch, b2, out, n);
}

// round 16
// speedup vs baseline: 4.5780x; 1.4522x over previous
#include <cuda_runtime.h>
#include <cuda_fp16.h>
#include <cstdint>

#define NB 64
#define DIN 64
#define DH 128
#define TM 128

// byte offsets in dynamic smem (16B aligned)
#define OFFB_S  0            // staging: 128 rows * 320 B fp32 = 40960
#define OFFB_PA 40960        // packed A fp16 cells: 5*64*4*16 = 20480
#define OFFB_W1 61440        // W1 fp16 cells: 5*64*4*16 = 20480
#define OFFB_H  81920        // H fp16 cells: 8*64*4*16 = 32768
#define OFFB_B2 114688       // 128 floats
#define OFFB_SB 115200       // 2*128 ints
#define SMEM_BYTES 116224

#define CA_GRID 592

__device__ float g_psum[NB*4];
__device__ unsigned long long g_amin[NB];
__device__ unsigned g_bar;
__device__ __align__(16) float g_cg[NB*DH];
__device__ __align__(16) float g_Wd[DIN*DH];      // W1a - W1b (fp32)
__device__ __align__(16) uint4 g_W1ph[5*64*4];    // fp16 B-cells [ds][pair][tig]
__device__ __align__(16) uint4 g_W2ph[8*64*4];

__device__ __forceinline__ unsigned h2u(float a, float b){
    __half2 h = __floats2half2_rn(a, b);
    return *reinterpret_cast<unsigned*>(&h);
}
__device__ __forceinline__ uint32_t s2u(const void* p){
    uint32_t a; asm("{ .reg .u64 t; cvta.to.shared.u64 t, %1; cvt.u32.u64 %0, t; }" : "=r"(a) : "l"(p)); return a;
}
__device__ __forceinline__ void atomicMaxF(float* a, float v){
    if (v >= 0.f) atomicMax((int*)a, __float_as_int(v));
    else          atomicMin((unsigned int*)a, __float_as_uint(v));
}
__device__ __forceinline__ void mma16(float (&c)[4], uint4 a, unsigned b0, unsigned b1){
    asm volatile("mma.sync.aligned.m16n8k16.row.col.f32.f16.f16.f32 "
        "{%0,%1,%2,%3}, {%4,%5,%6,%7}, {%8,%9}, {%0,%1,%2,%3};\n"
        : "+f"(c[0]), "+f"(c[1]), "+f"(c[2]), "+f"(c[3])
        : "r"(a.x), "r"(a.y), "r"(a.z), "r"(a.w), "r"(b0), "r"(b1));
}

// ---------------------------------------------------------------------------
// launch 0: init + Wd + fp16 weight cell packs
__global__ void k_init(const float* __restrict__ W1, const float* __restrict__ W2,
                       float* out, int out_size){
    int i = blockIdx.x*blockDim.x + threadIdx.x;
    if (i < NB*4) g_psum[i] = 0.f;
    if (i < NB)   g_amin[i] = 0xFFFFFFFFFFFFFFFFULL;
    if (i == 0)   g_bar = 0u;
    if (i < NB*DH && i < out_size) out[i] = __int_as_float(0xff800000);
    if (i < DIN*DH){
        int k = i >> 7, c = i & 127;
        g_Wd[i] = W1[k*DH + c] - W1[(DIN+k)*DH + c];
    }
    // W1 cells: eff rows (k<64 -> W1[64+k]; 64..66 -> W1[128+k-64]; else 0)
    if (i < 5*64*4){
        int tg = i & 3, pr = (i >> 2) & 63, ds = i >> 8;
        int c0 = ((pr >> 3) << 4) + (pr & 7), c1 = c0 + 8;
        int k0 = ds*16 + tg*2;
        auto effW1 = [&](int k, int c) -> float {
            if (k < 64)  return W1[(64+k)*DH + c];
            if (k < 67)  return W1[(128 + (k-64))*DH + c];
            return 0.f;
        };
        uint4 cell;
        cell.x = h2u(effW1(k0,   c0), effW1(k0+1, c0));
        cell.y = h2u(effW1(k0+8, c0), effW1(k0+9, c0));
        cell.z = h2u(effW1(k0,   c1), effW1(k0+1, c1));
        cell.w = h2u(effW1(k0+8, c1), effW1(k0+9, c1));
        g_W1ph[i] = cell;
    }
    if (i < 8*64*4){
        int tg = i & 3, pr = (i >> 2) & 63, ds = i >> 8;
        int c0 = ((pr >> 3) << 4) + (pr & 7), c1 = c0 + 8;
        int k0 = ds*16 + tg*2;
        uint4 cell;
        cell.x = h2u(W2[k0*DH + c0],     W2[(k0+1)*DH + c0]);
        cell.y = h2u(W2[(k0+8)*DH + c0], W2[(k0+9)*DH + c0]);
        cell.z = h2u(W2[k0*DH + c1],     W2[(k0+1)*DH + c1]);
        cell.w = h2u(W2[(k0+8)*DH + c1], W2[(k0+9)*DH + c1]);
        g_W2ph[i] = cell;
    }
}

// launch 1: COM + argmin + per-graph prep, 2 device-wide spin barriers
__global__ __launch_bounds__(256, 4) void k_comamin(
    const float* __restrict__ pos, const int* __restrict__ batch,
    const float* __restrict__ x, const float* __restrict__ lf,
    const float* __restrict__ W1, const float* __restrict__ b1,
    float* out, int out_size, int n){
    const int stride = CA_GRID*256;
    const int base = blockIdx.x*256 + threadIdx.x;
    const int trips = (n + stride - 1) / stride;

    for (int j = 0; j < trips; j++){
        int i = base + j*stride;
        int b = -1; float px=0.f, py=0.f, pz=0.f, pc=0.f;
        if (i < n){ b = batch[i]; px = pos[3*i]; py = pos[3*i+1]; pz = pos[3*i+2]; pc = 1.f; }
        int b0 = __shfl_sync(0xffffffffu, b, 0);
        bool uni = __all_sync(0xffffffffu, b == b0);
        if (uni){
            #pragma unroll
            for (int o = 16; o; o >>= 1){
                px += __shfl_down_sync(0xffffffffu, px, o);
                py += __shfl_down_sync(0xffffffffu, py, o);
                pz += __shfl_down_sync(0xffffffffu, pz, o);
                pc += __shfl_down_sync(0xffffffffu, pc, o);
            }
            if ((threadIdx.x & 31) == 0 && b0 >= 0){
                atomicAdd(&g_psum[b0*4+0], px); atomicAdd(&g_psum[b0*4+1], py);
                atomicAdd(&g_psum[b0*4+2], pz); atomicAdd(&g_psum[b0*4+3], pc);
            }
        } else if (b >= 0){
            atomicAdd(&g_psum[b*4+0], px); atomicAdd(&g_psum[b*4+1], py);
            atomicAdd(&g_psum[b*4+2], pz); atomicAdd(&g_psum[b*4+3], pc);
        }
    }

    __threadfence();
    __syncthreads();
    if (threadIdx.x == 0){
        atomicAdd(&g_bar, 1u);
        while (atomicAdd(&g_bar, 0u) < (unsigned)CA_GRID) __nanosleep(64);
    }
    __syncthreads();
    __threadfence();

    for (int j = 0; j < trips; j++){
        int i = base + j*stride;
        int b = -1; unsigned long long key = 0xFFFFFFFFFFFFFFFFULL;
        if (i < n){
            b = batch[i];
            float cnt = fmaxf(g_psum[b*4+3], 1.f);
            float inv = 1.f / cnt;
            float dx = pos[3*i]   - g_psum[b*4+0]*inv;
            float dy = pos[3*i+1] - g_psum[b*4+1]*inv;
            float dz = pos[3*i+2] - g_psum[b*4+2]*inv;
            float d2 = dx*dx + dy*dy + dz*dz;
            key = ((unsigned long long)__float_as_uint(d2) << 32) | (unsigned)i;
        }
        int b0 = __shfl_sync(0xffffffffu, b, 0);
        bool uni = __all_sync(0xffffffffu, b == b0);
        if (uni){
            #pragma unroll
            for (int o = 16; o; o >>= 1){
                unsigned long long k2 = __shfl_down_sync(0xffffffffu, key, o);
                if (k2 < key) key = k2;
            }
            if ((threadIdx.x & 31) == 0 && b0 >= 0) atomicMin(&g_amin[b0], key);
        } else if (b >= 0){
            atomicMin(&g_amin[b], key);
        }
    }

    __threadfence();
    __syncthreads();
    if (threadIdx.x == 0){
        atomicAdd(&g_bar, 1u);
        while (atomicAdd(&g_bar, 0u) < 2u*(unsigned)CA_GRID) __nanosleep(64);
    }
    __syncthreads();
    __threadfence();

    // phase 3: per-graph bias cg + aux outputs (blocks 0..31, 2 graphs each)
    if (blockIdx.x < NB/2){
        const int half = threadIdx.x >> 7;
        const int c = threadIdx.x & 127;
        const int g = blockIdx.x*2 + half;
        __shared__ float sxd[2][DIN];
        __shared__ float sp3[2][3];
        __shared__ int sidx[2];
        if (c == 0){
            int id = (int)(unsigned)(g_amin[g] & 0xFFFFFFFFULL);
            if (id > n-1) id = n-1;
            sidx[half] = id;
        }
        __syncthreads();
        int idx = sidx[half];
        if (c < DIN) sxd[half][c] = x[(size_t)idx*DIN + c];
        if (c < 3)   sp3[half][c] = pos[idx*3 + c];
        __syncthreads();
        float acc = b1[c];
        #pragma unroll 8
        for (int k = 0; k < DIN; k++)
            acc += sxd[half][k] * g_Wd[k*DH + c];
        #pragma unroll
        for (int j = 0; j < 3; j++)
            acc -= sp3[half][j] * W1[(2*DIN+j)*DH + c];
        g_cg[g*DH + c] = acc;

        if (out_size >= NB*DH + NB*3 + NB + NB*9){
            if (c < 3)  out[NB*DH + g*3 + c] = pos[idx*3 + c];
            if (c == 3) out[NB*DH + NB*3 + g] = (float)batch[idx];
            if (c < 9)  out[NB*DH + NB*3 + NB + g*9 + c] = lf[(size_t)idx*9 + c];
        }
    }
}

// ---------------------------------------------------------------------------
__device__ __forceinline__ void issue_load(char* smem, uint32_t sS_u,
        const float* __restrict__ x, const float* __restrict__ pos,
        const int* __restrict__ batch, int n, int base, int slot, int tid)
{
    #pragma unroll
    for (int rep = 0; rep < 4; rep++){
        int i = tid + rep*512;
        int r = i >> 4, ch = i & 15;
        int row = base + r;
        uint32_t dst = sS_u + (uint32_t)(r*320 + ch*16);
        const float* src = x + (size_t)(row < n ? row : 0)*DIN + ch*4;
        unsigned pb = (row < n) ? 16u : 0u;
        asm volatile("cp.async.cg.shared.global [%0], [%1], 16, %2;\n"
                     :: "r"(dst), "l"(src), "r"(pb) : "memory");
    }
    asm volatile("cp.async.commit_group;\n" ::: "memory");
    if (tid < TM){
        int row = base + tid;
        float4 p = make_float4(0.f, 0.f, 0.f, 0.f);
        int g = -1;
        if (row < n){ p.x = pos[3*row]; p.y = pos[3*row+1]; p.z = pos[3*row+2]; g = batch[row]; }
        *(float4*)(smem + OFFB_S + tid*320 + 256) = p;
        ((int*)(smem + OFFB_SB))[slot*128 + tid] = g;
    }
}

// launch 2: main fused kernel, 512 threads, warp tile 64x16, fp16 m16n8k16
__global__ __launch_bounds__(512, 1)
void k_main(const float* __restrict__ x, const float* __restrict__ pos,
            const int* __restrict__ batch, const float* __restrict__ b2,
            float* __restrict__ out, int n)
{
    extern __shared__ __align__(16) char smem[];
    const float* Sf  = (const float*)(smem + OFFB_S);
    uint4*       pA  = (uint4*)(smem + OFFB_PA);
    const uint4* sW1 = (const uint4*)(smem + OFFB_W1);
    uint4*       sH  = (uint4*)(smem + OFFB_H);
    float*       sB2 = (float*)(smem + OFFB_B2);

    const int tid = threadIdx.x, lane = tid & 31, warp = tid >> 5;
    const int gid = lane >> 2, tig = lane & 3;
    const int wm = warp & 1, wn = warp >> 1;   // 2 row bands (64) x 8 col bands (16)
    const int m0 = wm*64, n0 = wn*16;
    const int numTiles = (n + TM - 1) / TM;
    const uint32_t sS_u = s2u(smem + OFFB_S);

    // prologue: W1 cells to smem, b2, zero staging pad floats 68..79 per row
    {
        uint4* w1 = (uint4*)(smem + OFFB_W1);
        #pragma unroll
        for (int rep = 0; rep < 3; rep++){
            int i = tid + rep*512;
            if (i < 5*64*4) w1[i] = g_W1ph[i];
        }
        if (tid < DH) sB2[tid] = b2[tid];
        if (tid < TM){
            float4* z = (float4*)(smem + OFFB_S + tid*320 + 272);
            z[0] = z[1] = z[2] = make_float4(0.f,0.f,0.f,0.f);
        }
    }
    // entire W2 warp slice in registers: 8 cells
    uint4 wreg[8];
    #pragma unroll
    for (int ds = 0; ds < 8; ds++)
        wreg[ds] = g_W2ph[ds*256 + (wn*8 + gid)*4 + tig];

    const int t0 = blockIdx.x;
    if (t0 < numTiles) issue_load(smem, sS_u, x, pos, batch, n, t0*TM, 0, tid);
    asm volatile("cp.async.wait_group 0;\n" ::: "memory");
    __syncthreads();

    float acc[4][2][4];
    int it = 0;
    for (int t = t0; t < numTiles; t += 148, it++){
        const int par = it & 1;
        const int tn = t + 148;
        const int* sBc = (const int*)(smem + OFFB_SB) + par*128;

        // ===== convert staged fp32 -> packed fp16 A cells =====
        #pragma unroll
        for (int rep = 0; rep < 3; rep++){
            int c = tid + rep*512;
            if (c < 1280){
                int tg = c & 3, pr = (c >> 2) & 63, ds = c >> 8;
                int r = ((pr >> 3) << 4) + (pr & 7);
                int k0 = ds*16 + tg*2;
                float2 v0 = *(const float2*)(Sf + r*80 + k0);
                float2 v1 = *(const float2*)(Sf + (r+8)*80 + k0);
                float2 v2 = *(const float2*)(Sf + r*80 + k0 + 8);
                float2 v3 = *(const float2*)(Sf + (r+8)*80 + k0 + 8);
                uint4 cell;
                cell.x = h2u(v0.x, v0.y);
                cell.y = h2u(v1.x, v1.y);
                cell.z = h2u(v2.x, v2.y);
                cell.w = h2u(v3.x, v3.y);
                pA[c] = cell;
            }
        }
        __syncthreads();   // (A) pA ready, staging free

        // prefetch next tile into staging (overlaps L1/epi1/L2)
        if (tn < numTiles) issue_load(smem, sS_u, x, pos, batch, n, tn*TM, 1 - par, tid);

        // ===== layer 1: acc = A @ W1 (5 k16 steps) =====
        #pragma unroll
        for (int mt = 0; mt < 4; mt++)
            #pragma unroll
            for (int nt = 0; nt < 2; nt++)
                #pragma unroll
                for (int q = 0; q < 4; q++) acc[mt][nt][q] = 0.f;

        #pragma unroll
        for (int ds = 0; ds < 5; ds++){
            uint4 w = sW1[ds*256 + (wn*8 + gid)*4 + tig];
            #pragma unroll
            for (int mt = 0; mt < 4; mt++){
                uint4 a = pA[ds*256 + ((4*wm + mt)*8 + gid)*4 + tig];
                mma16(acc[mt][0], a, w.x, w.y);
                mma16(acc[mt][1], a, w.z, w.w);
            }
        }

        // ===== epilogue 1: h = relu(acc + cg[g]) -> H cells (fp16) =====
        #pragma unroll
        for (int mt = 0; mt < 4; mt++){
            int r0 = m0 + mt*16 + gid, r1 = r0 + 8;
            int g0 = sBc[r0], g1 = sBc[r1];
            const float2* cg0 = (const float2*)(g_cg + (size_t)(g0 < 0 ? 0 : g0)*DH);
            const float2* cg1 = (const float2*)(g_cg + (size_t)(g1 < 0 ? 0 : g1)*DH);
            int c0 = n0 + tig*2, c1 = n0 + 8 + tig*2;
            float2 cA0 = __ldg(&cg0[c0 >> 1]);
            float2 cA1 = __ldg(&cg0[c1 >> 1]);
            float2 cB0 = __ldg(&cg1[c0 >> 1]);
            float2 cB1 = __ldg(&cg1[c1 >> 1]);
            uint4 cell;
            cell.x = h2u(fmaxf(acc[mt][0][0] + cA0.x, 0.f), fmaxf(acc[mt][0][1] + cA0.y, 0.f));
            cell.y = h2u(fmaxf(acc[mt][0][2] + cB0.x, 0.f), fmaxf(acc[mt][0][3] + cB0.y, 0.f));
            cell.z = h2u(fmaxf(acc[mt][1][0] + cA1.x, 0.f), fmaxf(acc[mt][1][1] + cA1.y, 0.f));
            cell.w = h2u(fmaxf(acc[mt][1][2] + cB1.x, 0.f), fmaxf(acc[mt][1][3] + cB1.y, 0.f));
            sH[wn*256 + ((4*wm + mt)*8 + gid)*4 + tig] = cell;
        }
        __syncthreads();   // (B) sH ready

        // ===== layer 2: acc = H @ W2reg (8 k16 steps) =====
        #pragma unroll
        for (int mt = 0; mt < 4; mt++)
            #pragma unroll
            for (int nt = 0; nt < 2; nt++)
                #pragma unroll
                for (int q = 0; q < 4; q++) acc[mt][nt][q] = 0.f;

        #pragma unroll
        for (int ds = 0; ds < 8; ds++){
            #pragma unroll
            for (int mt = 0; mt < 4; mt++){
                uint4 a = sH[ds*256 + ((4*wm + mt)*8 + gid)*4 + tig];
                mma16(acc[mt][0], a, wreg[ds].x, wreg[ds].y);
                mma16(acc[mt][1], a, wreg[ds].z, wreg[ds].w);
            }
        }

        // ===== epilogue 2: segment-max from registers =====
        if (sBc[0] == sBc[TM-1]){
            int g = sBc[0];
            #pragma unroll
            for (int nt = 0; nt < 2; nt++)
                #pragma unroll
                for (int qc = 0; qc < 2; qc++){
                    float v = __int_as_float(0xff800000);
                    #pragma unroll
                    for (int mt = 0; mt < 4; mt++)
                        v = fmaxf(v, fmaxf(acc[mt][nt][qc], acc[mt][nt][2+qc]));
                    v = fmaxf(v, __shfl_down_sync(0xffffffffu, v, 4));
                    v = fmaxf(v, __shfl_down_sync(0xffffffffu, v, 8));
                    v = fmaxf(v, __shfl_down_sync(0xffffffffu, v, 16));
                    if (gid == 0){
                        int c = n0 + nt*8 + tig*2 + qc;
                        atomicMaxF(&out[g*DH + c], v + sB2[c]);
                    }
                }
        } else {
            #pragma unroll
            for (int R = 0; R < 8; R++){
                const int mt = R >> 1, qr = R & 1;
                int r = m0 + mt*16 + qr*8 + gid;
                int g   = sBc[r];
                int gp  = __shfl_up_sync(0xffffffffu, g, 4);
                int g4  = __shfl_down_sync(0xffffffffu, g, 4);
                int g8  = __shfl_down_sync(0xffffffffu, g, 8);
                int g16 = __shfl_down_sync(0xffffffffu, g, 16);
                bool m4  = (gid < 7) && (g4 == g);
                bool m8  = (gid < 6) && (g8 == g);
                bool m16 = (gid < 4) && (g16 == g);
                bool head = (g >= 0) && (gid == 0 || gp != g);
                #pragma unroll
                for (int nt = 0; nt < 2; nt++)
                    #pragma unroll
                    for (int qc = 0; qc < 2; qc++){
                        float v = acc[mt][nt][qr*2 + qc];
                        float tv;
                        tv = __shfl_down_sync(0xffffffffu, v, 4);  if (m4)  v = fmaxf(v, tv);
                        tv = __shfl_down_sync(0xffffffffu, v, 8);  if (m8)  v = fmaxf(v, tv);
                        tv = __shfl_down_sync(0xffffffffu, v, 16); if (m16) v = fmaxf(v, tv);
                        if (head){
                            int c = n0 + nt*8 + tig*2 + qc;
                            atomicMaxF(&out[g*DH + c], v + sB2[c]);
                        }
                    }
            }
        }

        asm volatile("cp.async.wait_group 0;\n" ::: "memory");
        __syncthreads();   // (C) next staging landed; sH free
    }
}

// ---------------------------------------------------------------------------
extern "C" void kernel_launch(void* const* d_in, const int* in_sizes, int n_in,
                              void* d_out, int out_size){
    const float* x     = (const float*)d_in[0];
    const float* pos   = (const float*)d_in[1];
    const int*   batch = (const int*)  d_in[2];
    const float* lf    = (const float*)d_in[3];
    const float* W1    = (const float*)d_in[4];
    const float* b1    = (const float*)d_in[5];
    const float* W2    = (const float*)d_in[6];
    const float* b2    = (const float*)d_in[7];
    float* out = (float*)d_out;
    int n = in_sizes[2];

    cudaFuncSetAttribute(k_main, cudaFuncAttributeMaxDynamicSharedMemorySize, SMEM_BYTES);

    k_init<<<104, 256>>>(W1, W2, out, out_size);
    k_comamin<<<CA_GRID, 256>>>(pos, batch, x, lf, W1, b1, out, out_size, n);
    k_main<<<148, 512, SMEM_BYTES>>>(x, pos, batch, b2, out, n);
}